// round 15
// baseline (speedup 1.0000x reference)
#include <cuda_runtime.h>
#include <cuda_bf16.h>
#include <stdint.h>
#include <math.h>

#define MB   2
#define SEQ  2048
#define DM   4096
#define NH   16
#define HDIM 256
#define ROTD 64

#define BK 32
#define NKT2 128            // K-chunks of 32
#define BLK2 8192           // one 128x32 bf16 block, 64B-row swizzled
#define WSZ ((size_t)DM * DM)

// ---------------- scratch ----------------
__device__ float g_Q[(size_t)MB * NH * SEQ * HDIM];
__device__ float g_K[(size_t)MB * NH * SEQ * HDIM];
__device__ float g_V[(size_t)MB * NH * SEQ * HDIM];
__device__ float g_CTX[(size_t)MB * SEQ * DM];
__device__ float2 g_rope[(size_t)MB * SEQ * 32];

// tiled + swizzled bf16 operand images (128x32 blocks, 8KB each)
__device__ __align__(1024) __nv_bfloat16 g_Xhi[(size_t)DM * DM];
__device__ __align__(1024) __nv_bfloat16 g_Xlo[(size_t)DM * DM];
__device__ __align__(1024) __nv_bfloat16 g_Chi[(size_t)DM * DM];
__device__ __align__(1024) __nv_bfloat16 g_Clo[(size_t)DM * DM];
__device__ __align__(1024) __nv_bfloat16 g_WThi[4][(size_t)DM * DM];
__device__ __align__(1024) __nv_bfloat16 g_WTlo[4][(size_t)DM * DM];

// attention packed operands
__device__ __align__(1024) __nv_bfloat16 g_Qph[(size_t)32 * 2048 * 256];
__device__ __align__(1024) __nv_bfloat16 g_Qpl[(size_t)32 * 2048 * 256];
__device__ __align__(1024) __nv_bfloat16 g_Kph[(size_t)32 * 2048 * 256];
__device__ __align__(1024) __nv_bfloat16 g_Kpl[(size_t)32 * 2048 * 256];
__device__ __align__(1024) __nv_bfloat16 g_Vph[(size_t)32 * 2048 * 256];
__device__ __align__(1024) __nv_bfloat16 g_Vpl[(size_t)32 * 2048 * 256];

// ---------------- helpers ----------------
__device__ __forceinline__ uint32_t smem_to_u32(const void* p) {
    uint32_t a;
    asm("{ .reg .u64 t; cvta.to.shared.u64 t, %1; cvt.u32.u64 %0, t; }" : "=r"(a) : "l"(p));
    return a;
}
#define MBARRIER_INIT(a, c) \
    asm volatile("mbarrier.init.shared.b64 [%0], %1;" :: "r"((uint32_t)(a)), "r"((uint32_t)(c)) : "memory")
#define MBARRIER_EXPECT_TX(a, tx) \
    asm volatile("mbarrier.arrive.expect_tx.shared.b64 _, [%0], %1;" :: "r"((uint32_t)(a)), "r"((uint32_t)(tx)) : "memory")
#define MBARRIER_ARRIVE(a) \
    asm volatile("mbarrier.arrive.shared.b64 _, [%0];" :: "r"((uint32_t)(a)) : "memory")
#define FENCE_PROXY_ASYNC() asm volatile("fence.proxy.async.shared::cta;" ::: "memory")
#define MBARRIER_WAIT_PARITY(mbar_smem_addr, phase_parity) do { \
    uint32_t _mbar = (uint32_t)(mbar_smem_addr); \
    uint32_t _parity = (uint32_t)(phase_parity); \
    uint32_t _done; \
    asm volatile("{\n\t.reg .pred p;\n\t" \
        "mbarrier.try_wait.parity.acquire.cta.shared::cta.b64 p, [%1], %2;\n\t" \
        "selp.b32 %0, 1, 0, p;\n\t}" \
        : "=r"(_done) : "r"(_mbar), "r"(_parity) : "memory"); \
    if (!_done) { \
        asm volatile("{\n\t.reg .pred P1;\n\t" \
            "WAIT_LOOP_%=:\n\t" \
            "mbarrier.try_wait.parity.acquire.cta.shared::cta.b64 P1, [%0], %1, 0x989680;\n\t" \
            "@P1 bra.uni WAIT_DONE_%=;\n\t" \
            "bra.uni WAIT_LOOP_%=;\n\t" \
            "WAIT_DONE_%=:\n\t}" \
            :: "r"(_mbar), "r"(_parity) : "memory"); \
    } \
} while(0)

__device__ __forceinline__ void tma_bulk(uint32_t dst, const void* src, uint32_t bytes, uint32_t mbar) {
    asm volatile("cp.async.bulk.shared::cluster.global.mbarrier::complete_tx::bytes [%0], [%1], %2, [%3];"
        :: "r"(dst), "l"(src), "r"(bytes), "r"(mbar) : "memory");
}

#define SMEM_SWIZZLE_128B(x) ((x) ^ (((x) >> 3) & 0x70))
__device__ __forceinline__ uint32_t swz64(int r, int c) {
    return (uint32_t)(r * 64 + ((c ^ ((r >> 1) & 3)) << 4));
}

#define LDSM4(r, addr) \
    asm volatile("ldmatrix.sync.aligned.m8n8.x4.shared.b16 {%0,%1,%2,%3}, [%4];" \
        : "=r"((r)[0]), "=r"((r)[1]), "=r"((r)[2]), "=r"((r)[3]) : "r"(addr))
#define LDSM2(r, addr) \
    asm volatile("ldmatrix.sync.aligned.m8n8.x2.shared.b16 {%0,%1}, [%2];" \
        : "=r"((r)[0]), "=r"((r)[1]) : "r"(addr))

__device__ __forceinline__ void mma16816(float* c, const uint32_t* a, uint32_t b0, uint32_t b1) {
    asm volatile("mma.sync.aligned.m16n8k16.row.col.f32.bf16.bf16.f32 "
        "{%0,%1,%2,%3}, {%4,%5,%6,%7}, {%8,%9}, {%0,%1,%2,%3};"
        : "+f"(c[0]), "+f"(c[1]), "+f"(c[2]), "+f"(c[3])
        : "r"(a[0]), "r"(a[1]), "r"(a[2]), "r"(a[3]), "r"(b0), "r"(b1));
}

__device__ __forceinline__ float ex2(float x) {
    float r;
    asm("ex2.approx.f32 %0, %1;" : "=f"(r) : "f"(x));
    return r;
}

__device__ __forceinline__ void split1(float v, __nv_bfloat16& h, __nv_bfloat16& l) {
    h = __float2bfloat16(v);
    l = __float2bfloat16(v - __bfloat162float(h));
}
__device__ __forceinline__ uint32_t pk2(float a, float b) {
    __nv_bfloat162 t = __floats2bfloat162_rn(a, b);
    return *(uint32_t*)&t;
}
__device__ __forceinline__ void pksplit2(float a, float b, uint32_t& hi, uint32_t& lo) {
    __nv_bfloat16 ah = __float2bfloat16(a), bh = __float2bfloat16(b);
    __nv_bfloat162 hp; hp.x = ah; hp.y = bh;
    hi = *(uint32_t*)&hp;
    lo = pk2(a - __bfloat162float(ah), b - __bfloat162float(bh));
}

// ---------------------------------------------------------------------------
// prep_all: merged split_rm(X) + 4x split_tr(W) + rope_tab in ONE grid.
// ---------------------------------------------------------------------------
__global__ void __launch_bounds__(256) prep_all(
    const float* __restrict__ X,
    __nv_bfloat16* __restrict__ Xhi, __nv_bfloat16* __restrict__ Xlo,
    const float* __restrict__ W0, const float* __restrict__ W1,
    const float* __restrict__ W2, const float* __restrict__ W3,
    __nv_bfloat16* __restrict__ WThi, __nv_bfloat16* __restrict__ WTlo,
    const int* __restrict__ pos, float2* __restrict__ tab)
{
    __shared__ float t[32][33];
    const int bid = blockIdx.x, tid = threadIdx.x;

    if (bid < 8192) {
        size_t idx = (size_t)bid * 256 + tid;
        int m  = (int)(idx >> 9);
        int k  = (int)(idx & 511) << 3;
        const float4* p = (const float4*)(X + ((size_t)m << 12) + k);
        float4 v0 = p[0], v1 = p[1];
        __nv_bfloat16 h[8], l[8];
        split1(v0.x, h[0], l[0]); split1(v0.y, h[1], l[1]);
        split1(v0.z, h[2], l[2]); split1(v0.w, h[3], l[3]);
        split1(v1.x, h[4], l[4]); split1(v1.y, h[5], l[5]);
        split1(v1.z, h[6], l[6]); split1(v1.w, h[7], l[7]);
        int mt = m >> 7, r = m & 127, kt = k >> 5, c = (k >> 3) & 3;
        size_t base = ((size_t)(mt * NKT2 + kt)) * BLK2 + swz64(r, c);
        *(uint4*)((char*)Xhi + base) = *(uint4*)h;
        *(uint4*)((char*)Xlo + base) = *(uint4*)l;
    } else if (bid < 73728) {
        const int q = bid - 8192;
        const int wsel = q >> 14;
        const int inner = q & 16383;
        const float* W = (wsel == 0) ? W0 : (wsel == 1) ? W1 : (wsel == 2) ? W2 : W3;
        __nv_bfloat16* Thi = WThi + (size_t)wsel * WSZ;
        __nv_bfloat16* Tlo = WTlo + (size_t)wsel * WSZ;
        const int nb = (inner & 127) * 32;
        const int kb = (inner >> 7) * 32;

        int tx = tid & 31, ty = tid >> 5;
#pragma unroll
        for (int j = 0; j < 4; j++)
            t[ty + j * 8][tx] = W[(size_t)(kb + ty + j * 8) * DM + nb + tx];
        __syncthreads();

        int half = tid >> 7, w7 = tid & 127;
        int nn = w7 >> 2, kc = (w7 & 3) * 8;
        int n = nb + nn, kk = kb + kc;
        float v[8];
#pragma unroll
        for (int qq = 0; qq < 8; qq++) v[qq] = t[kc + qq][nn];

        int nt = n >> 7, r = n & 127, kt = kk >> 5, c = (kk >> 3) & 3;
        size_t base = ((size_t)(nt * NKT2 + kt)) * BLK2 + swz64(r, c);
        __nv_bfloat16 o[8];
        if (half == 0) {
#pragma unroll
            for (int qq = 0; qq < 8; qq++) o[qq] = __float2bfloat16(v[qq]);
            *(uint4*)((char*)Thi + base) = *(uint4*)o;
        } else {
#pragma unroll
            for (int qq = 0; qq < 8; qq++) {
                __nv_bfloat16 hh = __float2bfloat16(v[qq]);
                o[qq] = __float2bfloat16(v[qq] - __bfloat162float(hh));
            }
            *(uint4*)((char*)Tlo + base) = *(uint4*)o;
        }
    } else {
        int idx = (bid - 73728) * 256 + tid;
        if (idx < MB * SEQ * 32) {
            int i = idx & 31, s = (idx >> 5) & (SEQ - 1), b = idx >> 16;
            int p = pos[b * SEQ + s];
            double inv = pow(10000.0, -(double)(2 * i) / (double)ROTD);
            double sn, cs;
            sincos((double)p * inv, &sn, &cs);
            tab[idx] = make_float2((float)cs, (float)sn);
        }
    }
}

// ---------------------------------------------------------------------------
// HMMA split-bf16 GEMM (round-9 best): 128x128 CTA, BK=32, 3 stages, 2 CTAs/SM
// ---------------------------------------------------------------------------
__global__ void __launch_bounds__(256, 2) gemm_hmma(
    const __nv_bfloat16* __restrict__ Ahi, const __nv_bfloat16* __restrict__ Alo,
    const __nv_bfloat16* __restrict__ Bhi, const __nv_bfloat16* __restrict__ Blo,
    float* __restrict__ C0, float* __restrict__ C1, float* __restrict__ C2,
    int mode)
{
    extern __shared__ char gsm[];
    uint32_t sb = (smem_to_u32(gsm) + 1023u) & ~1023u;
    const uint32_t stage0 = sb + 1024u;                   // 3 stages x 32KB
    const int tid = threadIdx.x, wid = tid >> 5, lane = tid & 31;
    const int bm = blockIdx.y * 128;
    const int bn_g = blockIdx.x * 128;
    const int wm = wid >> 2, wn = wid & 3;                // 2(M) x 4(N)

    if (tid == 0) {
#pragma unroll
        for (int s = 0; s < 3; s++) {
            MBARRIER_INIT(sb + s * 8, 1);
            MBARRIER_INIT(sb + 24 + s * 8, 256);
        }
        FENCE_PROXY_ASYNC();
    }
    __syncthreads();

    const char* pAh = (const char*)Ahi + ((size_t)blockIdx.y << 20);
    const char* pAl = (const char*)Alo + ((size_t)blockIdx.y << 20);
    const char* pBh = (const char*)Bhi + ((size_t)blockIdx.x << 20);
    const char* pBl = (const char*)Blo + ((size_t)blockIdx.x << 20);

    auto issue = [&](int j) {
        const int s = j % 3;
        const uint32_t st = stage0 + (uint32_t)s * 32768u;
        const uint32_t mb = sb + (uint32_t)s * 8u;
        const size_t off = (size_t)j << 13;
        MBARRIER_EXPECT_TX(mb, 32768u);
        tma_bulk(st,           pAh + off, 8192u, mb);
        tma_bulk(st + 8192u,   pAl + off, 8192u, mb);
        tma_bulk(st + 16384u,  pBh + off, 8192u, mb);
        tma_bulk(st + 24576u,  pBl + off, 8192u, mb);
    };
    if (tid == 0) { issue(0); issue(1); issue(2); }

    float acc[16][4];
#pragma unroll
    for (int i = 0; i < 16; i++)
#pragma unroll
        for (int j = 0; j < 4; j++) acc[i][j] = 0.f;

    const int ra = lane & 15, c4 = lane >> 4;
    const int rb = (lane & 7) + 8 * ((lane >> 3) & 1);

    int fph[3] = {0, 0, 0};
    int eph[3] = {0, 0, 0};
    for (int i = 0; i < NKT2; i++) {
        const int s = i % 3;
        const uint32_t st = stage0 + (uint32_t)s * 32768u;
        MBARRIER_WAIT_PARITY(sb + s * 8, fph[s]); fph[s] ^= 1;

#pragma unroll
        for (int ks = 0; ks < 2; ks++) {
            uint32_t bh[2][4], bl[2][4];
#pragma unroll
            for (int ip = 0; ip < 2; ip++) {
                uint32_t off = swz64(wn * 32 + ip * 16 + rb, ks * 2 + c4);
                LDSM4(bh[ip], st + 16384u + off);
                LDSM4(bl[ip], st + 24576u + off);
            }
#pragma unroll
            for (int im = 0; im < 4; im++) {
                uint32_t off = swz64(wm * 64 + im * 16 + ra, ks * 2 + c4);
                uint32_t ah[4], al[4];
                LDSM4(ah, st + off);
                LDSM4(al, st + 8192u + off);
#pragma unroll
                for (int in = 0; in < 4; in++) {
                    const int ip = in >> 1, sel = in & 1;
                    float* c = acc[im * 4 + in];
                    mma16816(c, ah, bh[ip][sel], bh[ip][sel + 2]);
                    mma16816(c, ah, bl[ip][sel], bl[ip][sel + 2]);
                    mma16816(c, al, bh[ip][sel], bh[ip][sel + 2]);
                }
            }
        }
        MBARRIER_ARRIVE(sb + 24 + s * 8);
        if (tid == 0 && i + 3 < NKT2) {
            MBARRIER_WAIT_PARITY(sb + 24 + s * 8, eph[s]); eph[s] ^= 1;
            issue(i + 3);
        }
    }

    const int tsel = bn_g >> 12;
    const int bn = bn_g & 4095;
    float* Cout = (tsel == 0) ? C0 : ((tsel == 1) ? C1 : C2);
#pragma unroll
    for (int im = 0; im < 4; im++) {
#pragma unroll
        for (int in = 0; in < 4; in++) {
            const float* c = acc[im * 4 + in];
            int m0 = bm + wm * 64 + im * 16 + (lane >> 2);
            int n  = bn + wn * 32 + in * 8 + (lane & 3) * 2;
#pragma unroll
            for (int half = 0; half < 2; half++) {
                int m = m0 + half * 8;
                float2 v = make_float2(c[half * 2], c[half * 2 + 1]);
                if (mode == 0) {
                    *(float2*)(C0 + (size_t)m * DM + n) = v;
                } else {
                    int b = m >> 11, sq = m & 2047, h = n >> 8, hd = n & 255;
                    *(float2*)(Cout + ((size_t)(b * NH + h) * SEQ + sq) * HDIM + hd) = v;
                }
            }
        }
    }
}

// ---------------------------------------------------------------------------
// split_rm (standalone, for CTX before the output projection)
// ---------------------------------------------------------------------------
__global__ void __launch_bounds__(256) split_rm_tiled(const float* __restrict__ in,
                                                      __nv_bfloat16* __restrict__ hi,
                                                      __nv_bfloat16* __restrict__ lo)
{
    size_t idx = (size_t)blockIdx.x * 256 + threadIdx.x;
    int m  = (int)(idx >> 9);
    int k  = (int)(idx & 511) << 3;
    const float4* p = (const float4*)(in + ((size_t)m << 12) + k);
    float4 v0 = p[0], v1 = p[1];

    __nv_bfloat16 h[8], l[8];
    split1(v0.x, h[0], l[0]); split1(v0.y, h[1], l[1]);
    split1(v0.z, h[2], l[2]); split1(v0.w, h[3], l[3]);
    split1(v1.x, h[4], l[4]); split1(v1.y, h[5], l[5]);
    split1(v1.z, h[6], l[6]); split1(v1.w, h[7], l[7]);

    int mt = m >> 7, r = m & 127, kt = k >> 5, c = (k >> 3) & 3;
    size_t base = ((size_t)(mt * NKT2 + kt)) * BLK2 + swz64(r, c);
    *(uint4*)((char*)hi + base) = *(uint4*)h;
    *(uint4*)((char*)lo + base) = *(uint4*)l;
}

// ---------------------------------------------------------------------------
// pack_all: merged pack_qk (rope fused) + pack_v in ONE grid.
// ---------------------------------------------------------------------------
__global__ void __launch_bounds__(256) pack_all(
    const float* __restrict__ Q, const float* __restrict__ K, const float* __restrict__ V,
    const float2* __restrict__ tab,
    __nv_bfloat16* __restrict__ Qh, __nv_bfloat16* __restrict__ Ql,
    __nv_bfloat16* __restrict__ Kh, __nv_bfloat16* __restrict__ Kl,
    __nv_bfloat16* __restrict__ Vh, __nv_bfloat16* __restrict__ Vl)
{
    __shared__ float sm[32][257];
    const int bid = blockIdx.x, t = threadIdx.x;

    if (bid < 8192) {
        size_t idx = (size_t)bid * 256 + t;
        int c0 = (int)(idx & 31) << 3;
        int s  = (int)(idx >> 5) & 2047;
        int bh = (int)(idx >> 16);
        int b  = bh >> 4;

        int st = s >> 5, r = s & 31, ct = c0 >> 6, cc = c0 & 63;
        size_t dst = (((size_t)(bh * 64 + st) * 4 + ct) << 12)
                   + SMEM_SWIZZLE_128B((uint32_t)(r * 128 + cc * 2));
        size_t src = ((size_t)bh * SEQ + s) * HDIM + c0;

        float2 rt[4];
        const bool dorope = (c0 < ROTD);
        if (dorope) {
#pragma unroll
            for (int q = 0; q < 4; q++)
                rt[q] = tab[(size_t)(b * SEQ + s) * 32 + (c0 >> 1) + q];
        }

        {
            const float4* p = (const float4*)(Q + src);
            float4 v0 = p[0], v1 = p[1];
            float vv[8] = {v0.x, v0.y, v0.z, v0.w, v1.x, v1.y, v1.z, v1.w};
            if (dorope) {
#pragma unroll
                for (int q = 0; q < 4; q++) {
                    float x = vv[2 * q], y = vv[2 * q + 1];
                    vv[2 * q]     = x * rt[q].x - y * rt[q].y;
                    vv[2 * q + 1] = y * rt[q].x + x * rt[q].y;
                }
            }
            __nv_bfloat16 h[8], l[8];
#pragma unroll
            for (int q = 0; q < 8; q++) split1(vv[q], h[q], l[q]);
            *(uint4*)((char*)Qh + dst) = *(uint4*)h;
            *(uint4*)((char*)Ql + dst) = *(uint4*)l;
        }
        {
            const float4* p = (const float4*)(K + src);
            float4 v0 = p[0], v1 = p[1];
            float vv[8] = {v0.x, v0.y, v0.z, v0.w, v1.x, v1.y, v1.z, v1.w};
            if (dorope) {
#pragma unroll
                for (int q = 0; q < 4; q++) {
                    float x = vv[2 * q], y = vv[2 * q + 1];
                    vv[2 * q]     = x * rt[q].x - y * rt[q].y;
                    vv[2 * q + 1] = y * rt[q].x + x * rt[q].y;
                }
            }
            __nv_bfloat16 h[8], l[8];
#pragma unroll
            for (int q = 0; q < 8; q++) split1(vv[q], h[q], l[q]);
            *(uint4*)((char*)Kh + dst) = *(uint4*)h;
            *(uint4*)((char*)Kl + dst) = *(uint4*)l;
        }
    } else {
        const int inner = bid - 8192;
        const int jt = inner & 63, bh = inner >> 6;
        int r = t >> 3, d0 = (t & 7) * 32;
        const float* src = V + ((size_t)bh * SEQ + jt * 32 + r) * HDIM + d0;
#pragma unroll
        for (int i = 0; i < 8; i++) {
            float4 v = *(const float4*)(src + i * 4);
            sm[r][d0 + i * 4 + 0] = v.x; sm[r][d0 + i * 4 + 1] = v.y;
            sm[r][d0 + i * 4 + 2] = v.z; sm[r][d0 + i * 4 + 3] = v.w;
        }
        __syncthreads();

        int d = t;
        int dt = d >> 7, rd = d & 127;
        size_t base = ((size_t)(bh * 64 + jt) * 2 + dt) << 13;
#pragma unroll
        for (int c = 0; c < 4; c++) {
            __nv_bfloat16 h[8], l[8];
#pragma unroll
            for (int jj = 0; jj < 8; jj++) split1(sm[c * 8 + jj][d], h[jj], l[jj]);
            size_t off = base + swz64(rd, c);
            *(uint4*)((char*)Vh + off) = *(uint4*)h;
            *(uint4*)((char*)Vl + off) = *(uint4*)l;
        }
    }
}

// ---------------------------------------------------------------------------
// HMMA causal flash attention, split-bf16, online softmax, 512 threads.
// 16 warps (mq=w&3 rows, kh=w>>2 keys): scores 16 rows x 8 keys per warp
// (K via ldmatrix.x2); 4-way softmax exchange; P via smem; PV over all 32
// keys x own 64-d quarter -> out[8][4]. 4 warps/SMSP at 1 CTA/SM.
// ---------------------------------------------------------------------------
__global__ void __launch_bounds__(512, 1) attn_mma(
    const __nv_bfloat16* __restrict__ Qph, const __nv_bfloat16* __restrict__ Qpl,
    const __nv_bfloat16* __restrict__ Kph, const __nv_bfloat16* __restrict__ Kpl,
    const __nv_bfloat16* __restrict__ Vph, const __nv_bfloat16* __restrict__ Vpl,
    float* __restrict__ CTX)
{
    extern __shared__ char gsm[];
    const uint32_t g0 = smem_to_u32(gsm);
    const uint32_t sb = (g0 + 1023u) & ~1023u;
    float* mbuf = (float*)(gsm + (sb - g0) + 128);          // 256 floats (4x64)
    float* sbuf = mbuf + 256;                               // 256 floats
    uint32_t* pbuf = (uint32_t*)(gsm + (sb - g0) + 3072);   // 16 warps x 128 u32 = 8KB
    const uint32_t sq = sb + 12288u;                        // Q: hi 32KB, lo 32KB
    const uint32_t sv = sq + 65536u;                        // 2 stages x 64KB

    const int qt = (int)gridDim.x - 1 - (int)blockIdx.x;
    const int bh = blockIdx.y;
    const int b  = bh >> 4, h = bh & 15;
    const int tid = threadIdx.x, w = tid >> 5, lane = tid & 31;
    const int mq = w & 3, kh = w >> 2;                      // rows group, keys octet
    const int nkt = 2 * qt + 2;

    if (tid == 0) {
        MBARRIER_INIT(sb, 1);
        MBARRIER_INIT(sb + 8, 1);
        MBARRIER_INIT(sb + 16, 1);
        MBARRIER_INIT(sb + 24, 512);
        MBARRIER_INIT(sb + 32, 512);
        FENCE_PROXY_ASYNC();
    }
    __syncthreads();

    auto issueKV = [&](int kt, int s) {
        const uint32_t st = sv + (uint32_t)s * 65536u;
        const uint32_t mb = sb + 8 + (uint32_t)s * 8u;
        MBARRIER_EXPECT_TX(mb, 65536u);
        size_t kbase = ((size_t)(bh * 64 + kt) * 4) << 12;
#pragma unroll
        for (int ct = 0; ct < 4; ct++) {
            tma_bulk(st + ct * 4096,          (const char*)Kph + kbase + ct * 4096, 4096u, mb);
            tma_bulk(st + 16384 + ct * 4096,  (const char*)Kpl + kbase + ct * 4096, 4096u, mb);
        }
        size_t vbase = ((size_t)(bh * 64 + kt) * 2) << 13;
#pragma unroll
        for (int dt = 0; dt < 2; dt++) {
            tma_bulk(st + 32768 + dt * 8192,  (const char*)Vph + vbase + dt * 8192, 8192u, mb);
            tma_bulk(st + 49152 + dt * 8192,  (const char*)Vpl + vbase + dt * 8192, 8192u, mb);
        }
    };

    if (tid == 0) {
        MBARRIER_EXPECT_TX(sb, 65536u);
#pragma unroll
        for (int sb2 = 0; sb2 < 2; sb2++) {
            size_t qbase = ((size_t)(bh * 64 + qt * 2 + sb2) * 4) << 12;
#pragma unroll
            for (int ct = 0; ct < 4; ct++) {
                tma_bulk(sq + (sb2 * 4 + ct) * 4096,          (const char*)Qph + qbase + ct * 4096, 4096u, sb);
                tma_bulk(sq + 32768 + (sb2 * 4 + ct) * 4096,  (const char*)Qpl + qbase + ct * 4096, 4096u, sb);
            }
        }
        issueKV(0, 0);
        issueKV(1, 1);
    }

    // out: this warp's 64-d quarter, its 16 rows -> 8 n-frags
    float out[8][4];
#pragma unroll
    for (int i = 0; i < 8; i++)
#pragma unroll
        for (int j = 0; j < 4; j++) out[i][j] = 0.f;
    float m0 = -1e30f, m1 = -1e30f, l0 = 0.f, l1 = 0.f;

    const int ra = lane & 15;
    const int rb = (lane & 7) + 8 * ((lane >> 3) & 1);
    const int qrow = (mq & 1) * 16 + ra;
    const int row0g = qt * 64 + mq * 16 + (lane >> 2);
    const int row1g = row0g + 8;
    const int xrow0 = mq * 16 + (lane >> 2);
    const int rowmax = qt * 64 + mq * 16 + 15;
    const int kaddr_base = (kh * 8 + (lane & 7)) * 128 + ((lane >> 3) & 1) * 16;
    const float SC = 0.0901699438f;

    MBARRIER_WAIT_PARITY(sb, 0);

    int fph0 = 0, fph1 = 0, eph0 = 0, eph1 = 0;
    for (int kt = 0; kt < nkt; kt++) {
        const int s = kt & 1;
        const uint32_t st = sv + (uint32_t)s * 65536u;
        if (s == 0) { MBARRIER_WAIT_PARITY(sb + 8, fph0);  fph0 ^= 1; }
        else        { MBARRIER_WAIT_PARITY(sb + 16, fph1); fph1 ^= 1; }

        const bool fullmask = (kt * 32 + kh * 8) > rowmax;   // warp-uniform

        float sc[4];
        float tm0 = -1e30f, tm1 = -1e30f;

        if (!fullmask) {
#pragma unroll
            for (int j = 0; j < 4; j++) sc[j] = 0.f;

#pragma unroll
            for (int kk = 0; kk < 16; kk++) {
                uint32_t ah[4], al[4], kfh[2], kfl[2];
                uint32_t aoff = (uint32_t)(((mq >> 1) * 4 + (kk >> 2)) * 4096)
                              + SMEM_SWIZZLE_128B((uint32_t)(qrow * 128 + (kk & 3) * 32 + (lane >> 4) * 16));
                LDSM4(ah, sq + aoff);
                LDSM4(al, sq + 32768u + aoff);
                uint32_t koff = (uint32_t)((kk >> 2) * 4096)
                              + SMEM_SWIZZLE_128B((uint32_t)(kaddr_base + (kk & 3) * 32));
                LDSM2(kfh, st + koff);
                LDSM2(kfl, st + 16384u + koff);
                mma16816(sc, ah, kfh[0], kfh[1]);
                mma16816(sc, ah, kfl[0], kfl[1]);
                mma16816(sc, al, kfh[0], kfh[1]);
            }

            const bool domask = (kt * 32 + kh * 8 + 7) > (qt * 64 + mq * 16);
#pragma unroll
            for (int j = 0; j < 4; j++) {
                float v = sc[j] * SC;
                if (domask) {
                    int col = kt * 32 + kh * 8 + (lane & 3) * 2 + (j & 1);
                    int row = (j < 2) ? row0g : row1g;
                    if (col > row) v = -1e30f;
                }
                sc[j] = v;
                if (j < 2) tm0 = fmaxf(tm0, v); else tm1 = fmaxf(tm1, v);
            }
            tm0 = fmaxf(tm0, __shfl_xor_sync(0xffffffffu, tm0, 1));
            tm0 = fmaxf(tm0, __shfl_xor_sync(0xffffffffu, tm0, 2));
            tm1 = fmaxf(tm1, __shfl_xor_sync(0xffffffffu, tm1, 1));
            tm1 = fmaxf(tm1, __shfl_xor_sync(0xffffffffu, tm1, 2));
        } else {
#pragma unroll
            for (int j = 0; j < 4; j++) sc[j] = -1e30f;
        }

        // ---- 4-way max exchange (sync 1) ----
        if ((lane & 3) == 0) {
            mbuf[kh * 64 + xrow0]     = tm0;
            mbuf[kh * 64 + xrow0 + 8] = tm1;
        }
        __syncthreads();
        tm0 = fmaxf(fmaxf(mbuf[xrow0],       mbuf[64 + xrow0]),
                    fmaxf(mbuf[128 + xrow0], mbuf[192 + xrow0]));
        tm1 = fmaxf(fmaxf(mbuf[xrow0 + 8],       mbuf[64 + xrow0 + 8]),
                    fmaxf(mbuf[128 + xrow0 + 8], mbuf[192 + xrow0 + 8]));

        float nm0 = fmaxf(m0, tm0), nm1 = fmaxf(m1, tm1);
        float a0 = ex2(m0 - nm0), a1 = ex2(m1 - nm1);
        float ls0, ls1;
        sc[0] = ex2(sc[0] - nm0); sc[1] = ex2(sc[1] - nm0); ls0 = sc[0] + sc[1];
        sc[2] = ex2(sc[2] - nm1); sc[3] = ex2(sc[3] - nm1); ls1 = sc[2] + sc[3];
        ls0 += __shfl_xor_sync(0xffffffffu, ls0, 1);
        ls0 += __shfl_xor_sync(0xffffffffu, ls0, 2);
        ls1 += __shfl_xor_sync(0xffffffffu, ls1, 1);
        ls1 += __shfl_xor_sync(0xffffffffu, ls1, 2);

        // ---- own P frags (8 keys: 2 hi + 2 lo regs) ----
        uint32_t ph0, ph1, pl0, pl1;
        pksplit2(sc[0], sc[1], ph0, pl0);
        pksplit2(sc[2], sc[3], ph1, pl1);

        // ---- sum + P exchange (sync 2) ----
        if ((lane & 3) == 0) {
            sbuf[kh * 64 + xrow0]     = ls0;
            sbuf[kh * 64 + xrow0 + 8] = ls1;
        }
        {
            uint32_t* slot = pbuf + w * 128 + lane;
            slot[0]  = ph0;
            slot[32] = ph1;
            slot[64] = pl0;
            slot[96] = pl1;
        }
        __syncthreads();
        ls0 = sbuf[xrow0] + sbuf[64 + xrow0] + sbuf[128 + xrow0] + sbuf[192 + xrow0];
        ls1 = sbuf[xrow0 + 8] + sbuf[64 + xrow0 + 8] + sbuf[128 + xrow0 + 8] + sbuf[192 + xrow0 + 8];

        l0 = l0 * a0 + ls0; l1 = l1 * a1 + ls1;
        m0 = nm0; m1 = nm1;

#pragma unroll
        for (int i = 0; i < 8; i++) {
            out[i][0] *= a0; out[i][1] *= a0;
            out[i][2] *= a1; out[i][3] *= a1;
        }

        // ---- out += P x V^T: all 32 keys, own 64-d quarter ----
        const uint32_t vbase = st + 32768u + (uint32_t)(kh >> 1) * 8192u;
        const int drow0 = (kh & 1) * 64;
#pragma unroll
        for (int kc = 0; kc < 2; kc++) {
            // A frags for 16 keys (groups 2kc, 2kc+1), rows mq -- from pbuf
            const uint32_t* s0 = pbuf + ((2 * kc) * 4 + mq) * 128 + lane;
            const uint32_t* s1 = pbuf + ((2 * kc + 1) * 4 + mq) * 128 + lane;
            uint32_t aH[4], aL[4];
            aH[0] = s0[0];  aH[1] = s0[32];
            aH[2] = s1[0];  aH[3] = s1[32];
            aL[0] = s0[64]; aL[1] = s0[96];
            aL[2] = s1[64]; aL[3] = s1[96];
#pragma unroll
            for (int dp = 0; dp < 4; dp++) {
                uint32_t vh[4], vl[4];
                int rr = drow0 + dp * 16 + rb;
                uint32_t voff = swz64(rr, kc * 2 + (lane >> 4));
                LDSM4(vh, vbase + voff);
                LDSM4(vl, vbase + 16384u + voff);
#pragma unroll
                for (int sel = 0; sel < 2; sel++) {
                    float* c = out[2 * dp + sel];
                    mma16816(c, aH, vh[sel], vh[sel + 2]);
                    mma16816(c, aH, vl[sel], vl[sel + 2]);
                    mma16816(c, aL, vh[sel], vh[sel + 2]);
                }
            }
        }

        MBARRIER_ARRIVE(sb + 24 + s * 8);
        if (tid == 0 && kt + 2 < nkt) {
            if (s == 0) { MBARRIER_WAIT_PARITY(sb + 24, eph0); eph0 ^= 1; }
            else        { MBARRIER_WAIT_PARITY(sb + 32, eph1); eph1 ^= 1; }
            issueKV(kt + 2, s);
        }
    }

    // ---- epilogue: direct write, warps own disjoint (rows, d-quarter) ----
    float inv0 = 1.0f / l0, inv1 = 1.0f / l1;
    float* base0 = CTX + ((size_t)(b * SEQ + row0g)) * DM + h * HDIM + kh * 64;
    float* base1 = CTX + ((size_t)(b * SEQ + row1g)) * DM + h * HDIM + kh * 64;
#pragma unroll
    for (int f = 0; f < 8; f++) {
        int d = f * 8 + (lane & 3) * 2;
        *(float2*)(base0 + d) = make_float2(out[f][0] * inv0, out[f][1] * inv0);
        *(float2*)(base1 + d) = make_float2(out[f][2] * inv1, out[f][3] * inv1);
    }
}

// ---------------------------------------------------------------------------
extern "C" void kernel_launch(void* const* d_in, const int* in_sizes, int n_in,
                              void* d_out, int out_size)
{
    const float* X   = (const float*)d_in[0];
    const int*   pos = (const int*)  d_in[1];
    const float* W[4] = { (const float*)d_in[2], (const float*)d_in[3],
                          (const float*)d_in[4], (const float*)d_in[5] };
    float* out = (float*)d_out;

    float *Qg, *Kg, *Vg, *CTX;
    float2* rope;
    __nv_bfloat16 *Xhi, *Xlo, *Chi, *Clo, *WThi, *WTlo;
    __nv_bfloat16 *Qph, *Qpl, *Kph, *Kpl, *Vph, *Vpl;
    cudaGetSymbolAddress((void**)&Qg,  g_Q);
    cudaGetSymbolAddress((void**)&Kg,  g_K);
    cudaGetSymbolAddress((void**)&Vg,  g_V);
    cudaGetSymbolAddress((void**)&CTX, g_CTX);
    cudaGetSymbolAddress((void**)&rope, g_rope);
    cudaGetSymbolAddress((void**)&Xhi, g_Xhi);
    cudaGetSymbolAddress((void**)&Xlo, g_Xlo);
    cudaGetSymbolAddress((void**)&Chi, g_Chi);
    cudaGetSymbolAddress((void**)&Clo, g_Clo);
    cudaGetSymbolAddress((void**)&WThi, g_WThi);
    cudaGetSymbolAddress((void**)&WTlo, g_WTlo);
    cudaGetSymbolAddress((void**)&Qph, g_Qph);
    cudaGetSymbolAddress((void**)&Qpl, g_Qpl);
    cudaGetSymbolAddress((void**)&Kph, g_Kph);
    cudaGetSymbolAddress((void**)&Kpl, g_Kpl);
    cudaGetSymbolAddress((void**)&Vph, g_Vph);
    cudaGetSymbolAddress((void**)&Vpl, g_Vpl);

    const int GEMM_SMEM = 1024 + 1024 + 3 * 32768;                    // 100352
    const int ATTN_SMEM = 1024 + 12288 + 65536 + 2 * 65536;           // 209920
    cudaFuncSetAttribute(gemm_hmma, cudaFuncAttributeMaxDynamicSharedMemorySize, GEMM_SMEM);
    cudaFuncSetAttribute(attn_mma, cudaFuncAttributeMaxDynamicSharedMemorySize, ATTN_SMEM);

    // merged prep: split_rm(X) + 4x split_tr(W) + rope table
    prep_all<<<74240, 256>>>(X, Xhi, Xlo, W[0], W[1], W[2], W[3],
                             WThi, WTlo, pos, rope);

    // fused QKV projection (fp32 scatter to [B,H,S,HD])
    gemm_hmma<<<dim3(96, 32), 256, GEMM_SMEM>>>(Xhi, Xlo, WThi, WTlo, Qg, Kg, Vg, 1);

    // merged pack: pack_qk (rope fused) + pack_v
    pack_all<<<10240, 256>>>(Qg, Kg, Vg, rope, Qph, Qpl, Kph, Kpl, Vph, Vpl);

    // attention (512 threads, writes fp32 CTX)
    attn_mma<<<dim3(32, 32), 512, ATTN_SMEM>>>(Qph, Qpl, Kph, Kpl, Vph, Vpl, CTX);

    // output projection
    split_rm_tiled<<<8192, 256>>>(CTX, Chi, Clo);
    gemm_hmma<<<dim3(32, 32), 256, GEMM_SMEM>>>(Chi, Clo, WThi + 3 * WSZ, WTlo + 3 * WSZ,
                                                out, nullptr, nullptr, 0);
}

// round 16
// speedup vs baseline: 1.5874x; 1.5874x over previous
#include <cuda_runtime.h>
#include <cuda_bf16.h>
#include <stdint.h>
#include <math.h>

#define MB   2
#define SEQ  2048
#define DM   4096
#define NH   16
#define HDIM 256
#define ROTD 64

#define BK 32
#define NKT2 128            // K-chunks of 32
#define BLK2 8192           // one 128x32 bf16 block, 64B-row swizzled
#define WSZ ((size_t)DM * DM)

// ---------------- scratch ----------------
__device__ float g_Q[(size_t)MB * NH * SEQ * HDIM];
__device__ float g_K[(size_t)MB * NH * SEQ * HDIM];
__device__ float g_V[(size_t)MB * NH * SEQ * HDIM];
__device__ float g_CTX[(size_t)MB * SEQ * DM];
__device__ float2 g_rope[(size_t)MB * SEQ * 32];

// tiled + swizzled bf16 operand images (128x32 blocks, 8KB each)
__device__ __align__(1024) __nv_bfloat16 g_Xhi[(size_t)DM * DM];
__device__ __align__(1024) __nv_bfloat16 g_Xlo[(size_t)DM * DM];
__device__ __align__(1024) __nv_bfloat16 g_Chi[(size_t)DM * DM];
__device__ __align__(1024) __nv_bfloat16 g_Clo[(size_t)DM * DM];
__device__ __align__(1024) __nv_bfloat16 g_WThi[4][(size_t)DM * DM];
__device__ __align__(1024) __nv_bfloat16 g_WTlo[4][(size_t)DM * DM];

// attention packed operands
__device__ __align__(1024) __nv_bfloat16 g_Qph[(size_t)32 * 2048 * 256];
__device__ __align__(1024) __nv_bfloat16 g_Qpl[(size_t)32 * 2048 * 256];
__device__ __align__(1024) __nv_bfloat16 g_Kph[(size_t)32 * 2048 * 256];
__device__ __align__(1024) __nv_bfloat16 g_Kpl[(size_t)32 * 2048 * 256];
__device__ __align__(1024) __nv_bfloat16 g_Vph[(size_t)32 * 2048 * 256];
__device__ __align__(1024) __nv_bfloat16 g_Vpl[(size_t)32 * 2048 * 256];

// ---------------- helpers ----------------
__device__ __forceinline__ uint32_t smem_to_u32(const void* p) {
    uint32_t a;
    asm("{ .reg .u64 t; cvta.to.shared.u64 t, %1; cvt.u32.u64 %0, t; }" : "=r"(a) : "l"(p));
    return a;
}
#define MBARRIER_INIT(a, c) \
    asm volatile("mbarrier.init.shared.b64 [%0], %1;" :: "r"((uint32_t)(a)), "r"((uint32_t)(c)) : "memory")
#define MBARRIER_EXPECT_TX(a, tx) \
    asm volatile("mbarrier.arrive.expect_tx.shared.b64 _, [%0], %1;" :: "r"((uint32_t)(a)), "r"((uint32_t)(tx)) : "memory")
#define MBARRIER_ARRIVE(a) \
    asm volatile("mbarrier.arrive.shared.b64 _, [%0];" :: "r"((uint32_t)(a)) : "memory")
#define FENCE_PROXY_ASYNC() asm volatile("fence.proxy.async.shared::cta;" ::: "memory")
#define MBARRIER_WAIT_PARITY(mbar_smem_addr, phase_parity) do { \
    uint32_t _mbar = (uint32_t)(mbar_smem_addr); \
    uint32_t _parity = (uint32_t)(phase_parity); \
    uint32_t _done; \
    asm volatile("{\n\t.reg .pred p;\n\t" \
        "mbarrier.try_wait.parity.acquire.cta.shared::cta.b64 p, [%1], %2;\n\t" \
        "selp.b32 %0, 1, 0, p;\n\t}" \
        : "=r"(_done) : "r"(_mbar), "r"(_parity) : "memory"); \
    if (!_done) { \
        asm volatile("{\n\t.reg .pred P1;\n\t" \
            "WAIT_LOOP_%=:\n\t" \
            "mbarrier.try_wait.parity.acquire.cta.shared::cta.b64 P1, [%0], %1, 0x989680;\n\t" \
            "@P1 bra.uni WAIT_DONE_%=;\n\t" \
            "bra.uni WAIT_LOOP_%=;\n\t" \
            "WAIT_DONE_%=:\n\t}" \
            :: "r"(_mbar), "r"(_parity) : "memory"); \
    } \
} while(0)

__device__ __forceinline__ void tma_bulk(uint32_t dst, const void* src, uint32_t bytes, uint32_t mbar) {
    asm volatile("cp.async.bulk.shared::cluster.global.mbarrier::complete_tx::bytes [%0], [%1], %2, [%3];"
        :: "r"(dst), "l"(src), "r"(bytes), "r"(mbar) : "memory");
}

#define SMEM_SWIZZLE_128B(x) ((x) ^ (((x) >> 3) & 0x70))
__device__ __forceinline__ uint32_t swz64(int r, int c) {
    return (uint32_t)(r * 64 + ((c ^ ((r >> 1) & 3)) << 4));
}

#define LDSM4(r, addr) \
    asm volatile("ldmatrix.sync.aligned.m8n8.x4.shared.b16 {%0,%1,%2,%3}, [%4];" \
        : "=r"((r)[0]), "=r"((r)[1]), "=r"((r)[2]), "=r"((r)[3]) : "r"(addr))

__device__ __forceinline__ void mma16816(float* c, const uint32_t* a, uint32_t b0, uint32_t b1) {
    asm volatile("mma.sync.aligned.m16n8k16.row.col.f32.bf16.bf16.f32 "
        "{%0,%1,%2,%3}, {%4,%5,%6,%7}, {%8,%9}, {%0,%1,%2,%3};"
        : "+f"(c[0]), "+f"(c[1]), "+f"(c[2]), "+f"(c[3])
        : "r"(a[0]), "r"(a[1]), "r"(a[2]), "r"(a[3]), "r"(b0), "r"(b1));
}

__device__ __forceinline__ float ex2(float x) {
    float r;
    asm("ex2.approx.f32 %0, %1;" : "=f"(r) : "f"(x));
    return r;
}

__device__ __forceinline__ void split1(float v, __nv_bfloat16& h, __nv_bfloat16& l) {
    h = __float2bfloat16(v);
    l = __float2bfloat16(v - __bfloat162float(h));
}
__device__ __forceinline__ uint32_t pk2(float a, float b) {
    __nv_bfloat162 t = __floats2bfloat162_rn(a, b);
    return *(uint32_t*)&t;
}
__device__ __forceinline__ void pksplit2(float a, float b, uint32_t& hi, uint32_t& lo) {
    __nv_bfloat16 ah = __float2bfloat16(a), bh = __float2bfloat16(b);
    __nv_bfloat162 hp; hp.x = ah; hp.y = bh;
    hi = *(uint32_t*)&hp;
    lo = pk2(a - __bfloat162float(ah), b - __bfloat162float(bh));
}

// ---------------------------------------------------------------------------
// prep_all: merged split_rm(X) + 4x split_tr(W) + rope_tab in ONE grid.
// ---------------------------------------------------------------------------
__global__ void __launch_bounds__(256) prep_all(
    const float* __restrict__ X,
    __nv_bfloat16* __restrict__ Xhi, __nv_bfloat16* __restrict__ Xlo,
    const float* __restrict__ W0, const float* __restrict__ W1,
    const float* __restrict__ W2, const float* __restrict__ W3,
    __nv_bfloat16* __restrict__ WThi, __nv_bfloat16* __restrict__ WTlo,
    const int* __restrict__ pos, float2* __restrict__ tab)
{
    __shared__ float t[32][33];
    const int bid = blockIdx.x, tid = threadIdx.x;

    if (bid < 8192) {
        size_t idx = (size_t)bid * 256 + tid;
        int m  = (int)(idx >> 9);
        int k  = (int)(idx & 511) << 3;
        const float4* p = (const float4*)(X + ((size_t)m << 12) + k);
        float4 v0 = p[0], v1 = p[1];
        __nv_bfloat16 h[8], l[8];
        split1(v0.x, h[0], l[0]); split1(v0.y, h[1], l[1]);
        split1(v0.z, h[2], l[2]); split1(v0.w, h[3], l[3]);
        split1(v1.x, h[4], l[4]); split1(v1.y, h[5], l[5]);
        split1(v1.z, h[6], l[6]); split1(v1.w, h[7], l[7]);
        int mt = m >> 7, r = m & 127, kt = k >> 5, c = (k >> 3) & 3;
        size_t base = ((size_t)(mt * NKT2 + kt)) * BLK2 + swz64(r, c);
        *(uint4*)((char*)Xhi + base) = *(uint4*)h;
        *(uint4*)((char*)Xlo + base) = *(uint4*)l;
    } else if (bid < 73728) {
        const int q = bid - 8192;
        const int wsel = q >> 14;
        const int inner = q & 16383;
        const float* W = (wsel == 0) ? W0 : (wsel == 1) ? W1 : (wsel == 2) ? W2 : W3;
        __nv_bfloat16* Thi = WThi + (size_t)wsel * WSZ;
        __nv_bfloat16* Tlo = WTlo + (size_t)wsel * WSZ;
        const int nb = (inner & 127) * 32;
        const int kb = (inner >> 7) * 32;

        int tx = tid & 31, ty = tid >> 5;
#pragma unroll
        for (int j = 0; j < 4; j++)
            t[ty + j * 8][tx] = W[(size_t)(kb + ty + j * 8) * DM + nb + tx];
        __syncthreads();

        int half = tid >> 7, w7 = tid & 127;
        int nn = w7 >> 2, kc = (w7 & 3) * 8;
        int n = nb + nn, kk = kb + kc;
        float v[8];
#pragma unroll
        for (int qq = 0; qq < 8; qq++) v[qq] = t[kc + qq][nn];

        int nt = n >> 7, r = n & 127, kt = kk >> 5, c = (kk >> 3) & 3;
        size_t base = ((size_t)(nt * NKT2 + kt)) * BLK2 + swz64(r, c);
        __nv_bfloat16 o[8];
        if (half == 0) {
#pragma unroll
            for (int qq = 0; qq < 8; qq++) o[qq] = __float2bfloat16(v[qq]);
            *(uint4*)((char*)Thi + base) = *(uint4*)o;
        } else {
#pragma unroll
            for (int qq = 0; qq < 8; qq++) {
                __nv_bfloat16 hh = __float2bfloat16(v[qq]);
                o[qq] = __float2bfloat16(v[qq] - __bfloat162float(hh));
            }
            *(uint4*)((char*)Tlo + base) = *(uint4*)o;
        }
    } else {
        int idx = (bid - 73728) * 256 + tid;
        if (idx < MB * SEQ * 32) {
            int i = idx & 31, s = (idx >> 5) & (SEQ - 1), b = idx >> 16;
            int p = pos[b * SEQ + s];
            double inv = pow(10000.0, -(double)(2 * i) / (double)ROTD);
            double sn, cs;
            sincos((double)p * inv, &sn, &cs);
            tab[idx] = make_float2((float)cs, (float)sn);
        }
    }
}

// ---------------------------------------------------------------------------
// HMMA split-bf16 GEMM (round-9 best): 128x128 CTA, BK=32, 3 stages, 2 CTAs/SM
// ---------------------------------------------------------------------------
__global__ void __launch_bounds__(256, 2) gemm_hmma(
    const __nv_bfloat16* __restrict__ Ahi, const __nv_bfloat16* __restrict__ Alo,
    const __nv_bfloat16* __restrict__ Bhi, const __nv_bfloat16* __restrict__ Blo,
    float* __restrict__ C0, float* __restrict__ C1, float* __restrict__ C2,
    int mode)
{
    extern __shared__ char gsm[];
    uint32_t sb = (smem_to_u32(gsm) + 1023u) & ~1023u;
    const uint32_t stage0 = sb + 1024u;                   // 3 stages x 32KB
    const int tid = threadIdx.x, wid = tid >> 5, lane = tid & 31;
    const int bm = blockIdx.y * 128;
    const int bn_g = blockIdx.x * 128;
    const int wm = wid >> 2, wn = wid & 3;                // 2(M) x 4(N)

    if (tid == 0) {
#pragma unroll
        for (int s = 0; s < 3; s++) {
            MBARRIER_INIT(sb + s * 8, 1);
            MBARRIER_INIT(sb + 24 + s * 8, 256);
        }
        FENCE_PROXY_ASYNC();
    }
    __syncthreads();

    const char* pAh = (const char*)Ahi + ((size_t)blockIdx.y << 20);
    const char* pAl = (const char*)Alo + ((size_t)blockIdx.y << 20);
    const char* pBh = (const char*)Bhi + ((size_t)blockIdx.x << 20);
    const char* pBl = (const char*)Blo + ((size_t)blockIdx.x << 20);

    auto issue = [&](int j) {
        const int s = j % 3;
        const uint32_t st = stage0 + (uint32_t)s * 32768u;
        const uint32_t mb = sb + (uint32_t)s * 8u;
        const size_t off = (size_t)j << 13;
        MBARRIER_EXPECT_TX(mb, 32768u);
        tma_bulk(st,           pAh + off, 8192u, mb);
        tma_bulk(st + 8192u,   pAl + off, 8192u, mb);
        tma_bulk(st + 16384u,  pBh + off, 8192u, mb);
        tma_bulk(st + 24576u,  pBl + off, 8192u, mb);
    };
    if (tid == 0) { issue(0); issue(1); issue(2); }

    float acc[16][4];
#pragma unroll
    for (int i = 0; i < 16; i++)
#pragma unroll
        for (int j = 0; j < 4; j++) acc[i][j] = 0.f;

    const int ra = lane & 15, c4 = lane >> 4;
    const int rb = (lane & 7) + 8 * ((lane >> 3) & 1);

    int fph[3] = {0, 0, 0};
    int eph[3] = {0, 0, 0};
    for (int i = 0; i < NKT2; i++) {
        const int s = i % 3;
        const uint32_t st = stage0 + (uint32_t)s * 32768u;
        MBARRIER_WAIT_PARITY(sb + s * 8, fph[s]); fph[s] ^= 1;

#pragma unroll
        for (int ks = 0; ks < 2; ks++) {
            uint32_t bh[2][4], bl[2][4];
#pragma unroll
            for (int ip = 0; ip < 2; ip++) {
                uint32_t off = swz64(wn * 32 + ip * 16 + rb, ks * 2 + c4);
                LDSM4(bh[ip], st + 16384u + off);
                LDSM4(bl[ip], st + 24576u + off);
            }
#pragma unroll
            for (int im = 0; im < 4; im++) {
                uint32_t off = swz64(wm * 64 + im * 16 + ra, ks * 2 + c4);
                uint32_t ah[4], al[4];
                LDSM4(ah, st + off);
                LDSM4(al, st + 8192u + off);
#pragma unroll
                for (int in = 0; in < 4; in++) {
                    const int ip = in >> 1, sel = in & 1;
                    float* c = acc[im * 4 + in];
                    mma16816(c, ah, bh[ip][sel], bh[ip][sel + 2]);
                    mma16816(c, ah, bl[ip][sel], bl[ip][sel + 2]);
                    mma16816(c, al, bh[ip][sel], bh[ip][sel + 2]);
                }
            }
        }
        MBARRIER_ARRIVE(sb + 24 + s * 8);
        if (tid == 0 && i + 3 < NKT2) {
            MBARRIER_WAIT_PARITY(sb + 24 + s * 8, eph[s]); eph[s] ^= 1;
            issue(i + 3);
        }
    }

    const int tsel = bn_g >> 12;
    const int bn = bn_g & 4095;
    float* Cout = (tsel == 0) ? C0 : ((tsel == 1) ? C1 : C2);
#pragma unroll
    for (int im = 0; im < 4; im++) {
#pragma unroll
        for (int in = 0; in < 4; in++) {
            const float* c = acc[im * 4 + in];
            int m0 = bm + wm * 64 + im * 16 + (lane >> 2);
            int n  = bn + wn * 32 + in * 8 + (lane & 3) * 2;
#pragma unroll
            for (int half = 0; half < 2; half++) {
                int m = m0 + half * 8;
                float2 v = make_float2(c[half * 2], c[half * 2 + 1]);
                if (mode == 0) {
                    *(float2*)(C0 + (size_t)m * DM + n) = v;
                } else {
                    int b = m >> 11, sq = m & 2047, h = n >> 8, hd = n & 255;
                    *(float2*)(Cout + ((size_t)(b * NH + h) * SEQ + sq) * HDIM + hd) = v;
                }
            }
        }
    }
}

// ---------------------------------------------------------------------------
// split_rm (standalone, for CTX before the output projection)
// ---------------------------------------------------------------------------
__global__ void __launch_bounds__(256) split_rm_tiled(const float* __restrict__ in,
                                                      __nv_bfloat16* __restrict__ hi,
                                                      __nv_bfloat16* __restrict__ lo)
{
    size_t idx = (size_t)blockIdx.x * 256 + threadIdx.x;
    int m  = (int)(idx >> 9);
    int k  = (int)(idx & 511) << 3;
    const float4* p = (const float4*)(in + ((size_t)m << 12) + k);
    float4 v0 = p[0], v1 = p[1];

    __nv_bfloat16 h[8], l[8];
    split1(v0.x, h[0], l[0]); split1(v0.y, h[1], l[1]);
    split1(v0.z, h[2], l[2]); split1(v0.w, h[3], l[3]);
    split1(v1.x, h[4], l[4]); split1(v1.y, h[5], l[5]);
    split1(v1.z, h[6], l[6]); split1(v1.w, h[7], l[7]);

    int mt = m >> 7, r = m & 127, kt = k >> 5, c = (k >> 3) & 3;
    size_t base = ((size_t)(mt * NKT2 + kt)) * BLK2 + swz64(r, c);
    *(uint4*)((char*)hi + base) = *(uint4*)h;
    *(uint4*)((char*)lo + base) = *(uint4*)l;
}

// ---------------------------------------------------------------------------
// pack_all: merged pack_qk (rope fused) + pack_v in ONE grid.
// ---------------------------------------------------------------------------
__global__ void __launch_bounds__(256) pack_all(
    const float* __restrict__ Q, const float* __restrict__ K, const float* __restrict__ V,
    const float2* __restrict__ tab,
    __nv_bfloat16* __restrict__ Qh, __nv_bfloat16* __restrict__ Ql,
    __nv_bfloat16* __restrict__ Kh, __nv_bfloat16* __restrict__ Kl,
    __nv_bfloat16* __restrict__ Vh, __nv_bfloat16* __restrict__ Vl)
{
    __shared__ float sm[32][257];
    const int bid = blockIdx.x, t = threadIdx.x;

    if (bid < 8192) {
        size_t idx = (size_t)bid * 256 + t;
        int c0 = (int)(idx & 31) << 3;
        int s  = (int)(idx >> 5) & 2047;
        int bh = (int)(idx >> 16);
        int b  = bh >> 4;

        int st = s >> 5, r = s & 31, ct = c0 >> 6, cc = c0 & 63;
        size_t dst = (((size_t)(bh * 64 + st) * 4 + ct) << 12)
                   + SMEM_SWIZZLE_128B((uint32_t)(r * 128 + cc * 2));
        size_t src = ((size_t)bh * SEQ + s) * HDIM + c0;

        float2 rt[4];
        const bool dorope = (c0 < ROTD);
        if (dorope) {
#pragma unroll
            for (int q = 0; q < 4; q++)
                rt[q] = tab[(size_t)(b * SEQ + s) * 32 + (c0 >> 1) + q];
        }

        {
            const float4* p = (const float4*)(Q + src);
            float4 v0 = p[0], v1 = p[1];
            float vv[8] = {v0.x, v0.y, v0.z, v0.w, v1.x, v1.y, v1.z, v1.w};
            if (dorope) {
#pragma unroll
                for (int q = 0; q < 4; q++) {
                    float x = vv[2 * q], y = vv[2 * q + 1];
                    vv[2 * q]     = x * rt[q].x - y * rt[q].y;
                    vv[2 * q + 1] = y * rt[q].x + x * rt[q].y;
                }
            }
            __nv_bfloat16 h[8], l[8];
#pragma unroll
            for (int q = 0; q < 8; q++) split1(vv[q], h[q], l[q]);
            *(uint4*)((char*)Qh + dst) = *(uint4*)h;
            *(uint4*)((char*)Ql + dst) = *(uint4*)l;
        }
        {
            const float4* p = (const float4*)(K + src);
            float4 v0 = p[0], v1 = p[1];
            float vv[8] = {v0.x, v0.y, v0.z, v0.w, v1.x, v1.y, v1.z, v1.w};
            if (dorope) {
#pragma unroll
                for (int q = 0; q < 4; q++) {
                    float x = vv[2 * q], y = vv[2 * q + 1];
                    vv[2 * q]     = x * rt[q].x - y * rt[q].y;
                    vv[2 * q + 1] = y * rt[q].x + x * rt[q].y;
                }
            }
            __nv_bfloat16 h[8], l[8];
#pragma unroll
            for (int q = 0; q < 8; q++) split1(vv[q], h[q], l[q]);
            *(uint4*)((char*)Kh + dst) = *(uint4*)h;
            *(uint4*)((char*)Kl + dst) = *(uint4*)l;
        }
    } else {
        const int inner = bid - 8192;
        const int jt = inner & 63, bh = inner >> 6;
        int r = t >> 3, d0 = (t & 7) * 32;
        const float* src = V + ((size_t)bh * SEQ + jt * 32 + r) * HDIM + d0;
#pragma unroll
        for (int i = 0; i < 8; i++) {
            float4 v = *(const float4*)(src + i * 4);
            sm[r][d0 + i * 4 + 0] = v.x; sm[r][d0 + i * 4 + 1] = v.y;
            sm[r][d0 + i * 4 + 2] = v.z; sm[r][d0 + i * 4 + 3] = v.w;
        }
        __syncthreads();

        int d = t;
        int dt = d >> 7, rd = d & 127;
        size_t base = ((size_t)(bh * 64 + jt) * 2 + dt) << 13;
#pragma unroll
        for (int c = 0; c < 4; c++) {
            __nv_bfloat16 h[8], l[8];
#pragma unroll
            for (int jj = 0; jj < 8; jj++) split1(sm[c * 8 + jj][d], h[jj], l[jj]);
            size_t off = base + swz64(rd, c);
            *(uint4*)((char*)Vh + off) = *(uint4*)h;
            *(uint4*)((char*)Vl + off) = *(uint4*)l;
        }
    }
}

// ---------------------------------------------------------------------------
// HMMA causal flash attention (round-14 best + masked-score skip).
// 256 threads, warp (mq, kh): scores for kh's 16 keys (skipped when the whole
// warp-tile is masked; P becomes exact zeros); P frags exchanged through smem;
// PV over ALL 32 keys but only the warp's own 128-d half -> out[16][4].
// ---------------------------------------------------------------------------
__global__ void __launch_bounds__(256, 1) attn_mma(
    const __nv_bfloat16* __restrict__ Qph, const __nv_bfloat16* __restrict__ Qpl,
    const __nv_bfloat16* __restrict__ Kph, const __nv_bfloat16* __restrict__ Kpl,
    const __nv_bfloat16* __restrict__ Vph, const __nv_bfloat16* __restrict__ Vpl,
    float* __restrict__ CTX)
{
    extern __shared__ char gsm[];
    const uint32_t g0 = smem_to_u32(gsm);
    const uint32_t sb = (g0 + 1023u) & ~1023u;
    float* mbuf = (float*)(gsm + (sb - g0) + 128);    // 128 floats
    float* sbuf = mbuf + 128;                         // 128 floats
    uint32_t* pbuf = (uint32_t*)(gsm + (sb - g0) + 2048);  // 8KB P exchange
    const uint32_t sq = sb + 10240u;                  // Q: hi 32KB, lo 32KB
    const uint32_t sv = sq + 65536u;                  // 2 stages x 64KB

    const int qt = (int)gridDim.x - 1 - (int)blockIdx.x;
    const int bh = blockIdx.y;
    const int b  = bh >> 4, h = bh & 15;
    const int tid = threadIdx.x, w = tid >> 5, lane = tid & 31;
    const int mq = w & 3, kh = w >> 2;
    const int nkt = 2 * qt + 2;

    if (tid == 0) {
        MBARRIER_INIT(sb, 1);
        MBARRIER_INIT(sb + 8, 1);
        MBARRIER_INIT(sb + 16, 1);
        MBARRIER_INIT(sb + 24, 256);
        MBARRIER_INIT(sb + 32, 256);
        FENCE_PROXY_ASYNC();
    }
    __syncthreads();

    auto issueKV = [&](int kt, int s) {
        const uint32_t st = sv + (uint32_t)s * 65536u;
        const uint32_t mb = sb + 8 + (uint32_t)s * 8u;
        MBARRIER_EXPECT_TX(mb, 65536u);
        size_t kbase = ((size_t)(bh * 64 + kt) * 4) << 12;
#pragma unroll
        for (int ct = 0; ct < 4; ct++) {
            tma_bulk(st + ct * 4096,          (const char*)Kph + kbase + ct * 4096, 4096u, mb);
            tma_bulk(st + 16384 + ct * 4096,  (const char*)Kpl + kbase + ct * 4096, 4096u, mb);
        }
        size_t vbase = ((size_t)(bh * 64 + kt) * 2) << 13;
#pragma unroll
        for (int dt = 0; dt < 2; dt++) {
            tma_bulk(st + 32768 + dt * 8192,  (const char*)Vph + vbase + dt * 8192, 8192u, mb);
            tma_bulk(st + 49152 + dt * 8192,  (const char*)Vpl + vbase + dt * 8192, 8192u, mb);
        }
    };

    if (tid == 0) {
        MBARRIER_EXPECT_TX(sb, 65536u);
#pragma unroll
        for (int sb2 = 0; sb2 < 2; sb2++) {
            size_t qbase = ((size_t)(bh * 64 + qt * 2 + sb2) * 4) << 12;
#pragma unroll
            for (int ct = 0; ct < 4; ct++) {
                tma_bulk(sq + (sb2 * 4 + ct) * 4096,          (const char*)Qph + qbase + ct * 4096, 4096u, sb);
                tma_bulk(sq + 32768 + (sb2 * 4 + ct) * 4096,  (const char*)Qpl + qbase + ct * 4096, 4096u, sb);
            }
        }
        issueKV(0, 0);
        issueKV(1, 1);
    }

    float out[16][4];
#pragma unroll
    for (int i = 0; i < 16; i++)
#pragma unroll
        for (int j = 0; j < 4; j++) out[i][j] = 0.f;
    float m0 = -1e30f, m1 = -1e30f, l0 = 0.f, l1 = 0.f;

    const int ra = lane & 15;
    const int rb = (lane & 7) + 8 * ((lane >> 3) & 1);
    const int qrow = (mq & 1) * 16 + ra;
    const int row0g = qt * 64 + mq * 16 + (lane >> 2);
    const int row1g = row0g + 8;
    const int xrow0 = mq * 16 + (lane >> 2);
    const int rowmax = qt * 64 + mq * 16 + 15;
    const int pme = w * 256 + lane;
    const int ppr = ((kh ^ 1) * 4 + mq) * 256 + lane;
    const float SC = 0.0901699438f;

    MBARRIER_WAIT_PARITY(sb, 0);

    int fph0 = 0, fph1 = 0, eph0 = 0, eph1 = 0;
    for (int kt = 0; kt < nkt; kt++) {
        const int s = kt & 1;
        const uint32_t st = sv + (uint32_t)s * 65536u;
        if (s == 0) { MBARRIER_WAIT_PARITY(sb + 8, fph0);  fph0 ^= 1; }
        else        { MBARRIER_WAIT_PARITY(sb + 16, fph1); fph1 ^= 1; }

        const bool fullmask = (kt * 32 + kh * 16) > rowmax;  // warp-uniform

        float sc[2][4];
        float tm0 = -1e30f, tm1 = -1e30f;

        if (!fullmask) {
#pragma unroll
            for (int f = 0; f < 2; f++)
#pragma unroll
                for (int j = 0; j < 4; j++) sc[f][j] = 0.f;

#pragma unroll
            for (int kk = 0; kk < 16; kk++) {
                uint32_t ah[4], al[4], kfh[4], kfl[4];
                uint32_t aoff = (uint32_t)(((mq >> 1) * 4 + (kk >> 2)) * 4096)
                              + SMEM_SWIZZLE_128B((uint32_t)(qrow * 128 + (kk & 3) * 32 + (lane >> 4) * 16));
                LDSM4(ah, sq + aoff);
                LDSM4(al, sq + 32768u + aoff);
                uint32_t koff = (uint32_t)((kk >> 2) * 4096)
                              + SMEM_SWIZZLE_128B((uint32_t)((kh * 16 + rb) * 128 + (kk & 3) * 32 + (lane >> 4) * 16));
                LDSM4(kfh, st + koff);
                LDSM4(kfl, st + 16384u + koff);
#pragma unroll
                for (int f = 0; f < 2; f++) {
                    mma16816(sc[f], ah, kfh[f], kfh[f + 2]);
                    mma16816(sc[f], ah, kfl[f], kfl[f + 2]);
                    mma16816(sc[f], al, kfh[f], kfh[f + 2]);
                }
            }

            const bool domask = (kt * 32 + kh * 16 + 15) > (qt * 64 + mq * 16);
#pragma unroll
            for (int f = 0; f < 2; f++) {
#pragma unroll
                for (int j = 0; j < 4; j++) {
                    float v = sc[f][j] * SC;
                    if (domask) {
                        int col = kt * 32 + kh * 16 + f * 8 + (lane & 3) * 2 + (j & 1);
                        int row = (j < 2) ? row0g : row1g;
                        if (col > row) v = -1e30f;
                    }
                    sc[f][j] = v;
                    if (j < 2) tm0 = fmaxf(tm0, v); else tm1 = fmaxf(tm1, v);
                }
            }
            tm0 = fmaxf(tm0, __shfl_xor_sync(0xffffffffu, tm0, 1));
            tm0 = fmaxf(tm0, __shfl_xor_sync(0xffffffffu, tm0, 2));
            tm1 = fmaxf(tm1, __shfl_xor_sync(0xffffffffu, tm1, 1));
            tm1 = fmaxf(tm1, __shfl_xor_sync(0xffffffffu, tm1, 2));
        } else {
#pragma unroll
            for (int f = 0; f < 2; f++)
#pragma unroll
                for (int j = 0; j < 4; j++) sc[f][j] = -1e30f;
        }

        // ---- cross-warp max exchange (sync 1) ----
        if ((lane & 3) == 0) {
            mbuf[kh * 64 + xrow0]     = tm0;
            mbuf[kh * 64 + xrow0 + 8] = tm1;
        }
        __syncthreads();
        tm0 = fmaxf(tm0, mbuf[(kh ^ 1) * 64 + xrow0]);
        tm1 = fmaxf(tm1, mbuf[(kh ^ 1) * 64 + xrow0 + 8]);

        float nm0 = fmaxf(m0, tm0), nm1 = fmaxf(m1, tm1);
        float a0 = ex2(m0 - nm0), a1 = ex2(m1 - nm1);
        float ls0 = 0.f, ls1 = 0.f;
#pragma unroll
        for (int f = 0; f < 2; f++) {
            sc[f][0] = ex2(sc[f][0] - nm0); ls0 += sc[f][0];
            sc[f][1] = ex2(sc[f][1] - nm0); ls0 += sc[f][1];
            sc[f][2] = ex2(sc[f][2] - nm1); ls1 += sc[f][2];
            sc[f][3] = ex2(sc[f][3] - nm1); ls1 += sc[f][3];
        }
        ls0 += __shfl_xor_sync(0xffffffffu, ls0, 1);
        ls0 += __shfl_xor_sync(0xffffffffu, ls0, 2);
        ls1 += __shfl_xor_sync(0xffffffffu, ls1, 1);
        ls1 += __shfl_xor_sync(0xffffffffu, ls1, 2);

        // ---- P frags (bf16 hi/lo) ----
        uint32_t pah[4], pal[4];
        pksplit2(sc[0][0], sc[0][1], pah[0], pal[0]);
        pksplit2(sc[0][2], sc[0][3], pah[1], pal[1]);
        pksplit2(sc[1][0], sc[1][1], pah[2], pal[2]);
        pksplit2(sc[1][2], sc[1][3], pah[3], pal[3]);

        // ---- sum + P exchange (sync 2) ----
        if ((lane & 3) == 0) {
            sbuf[kh * 64 + xrow0]     = ls0;
            sbuf[kh * 64 + xrow0 + 8] = ls1;
        }
#pragma unroll
        for (int i = 0; i < 4; i++) {
            pbuf[pme + i * 32]        = pah[i];
            pbuf[pme + (4 + i) * 32]  = pal[i];
        }
        __syncthreads();
        ls0 += sbuf[(kh ^ 1) * 64 + xrow0];
        ls1 += sbuf[(kh ^ 1) * 64 + xrow0 + 8];

        uint32_t qah[4], qal[4];
#pragma unroll
        for (int i = 0; i < 4; i++) {
            qah[i] = pbuf[ppr + i * 32];
            qal[i] = pbuf[ppr + (4 + i) * 32];
        }

        l0 = l0 * a0 + ls0; l1 = l1 * a1 + ls1;
        m0 = nm0; m1 = nm1;

#pragma unroll
        for (int i = 0; i < 16; i++) {
            out[i][0] *= a0; out[i][1] *= a0;
            out[i][2] *= a1; out[i][3] *= a1;
        }

        // ---- out += P x V^T: all 32 keys, own 128-d half (dt = kh) ----
        const uint32_t vbase = st + 32768u + (uint32_t)kh * 8192u;
#pragma unroll
        for (int kc = 0; kc < 2; kc++) {
            const uint32_t* uh = (kc == kh) ? pah : qah;
            const uint32_t* ul = (kc == kh) ? pal : qal;
#pragma unroll
            for (int dp = 0; dp < 8; dp++) {
                uint32_t vh[4], vl[4];
                int rr = dp * 16 + rb;
                uint32_t voff = swz64(rr, kc * 2 + (lane >> 4));
                LDSM4(vh, vbase + voff);
                LDSM4(vl, vbase + 16384u + voff);
#pragma unroll
                for (int sel = 0; sel < 2; sel++) {
                    float* c = out[2 * dp + sel];
                    mma16816(c, uh, vh[sel], vh[sel + 2]);
                    mma16816(c, uh, vl[sel], vl[sel + 2]);
                    mma16816(c, ul, vh[sel], vh[sel + 2]);
                }
            }
        }

        MBARRIER_ARRIVE(sb + 24 + s * 8);
        if (tid == 0 && kt + 2 < nkt) {
            if (s == 0) { MBARRIER_WAIT_PARITY(sb + 24, eph0); eph0 ^= 1; }
            else        { MBARRIER_WAIT_PARITY(sb + 32, eph1); eph1 ^= 1; }
            issueKV(kt + 2, s);
        }
    }

    // ---- epilogue: direct write, warps own disjoint (rows, d-half) ----
    float inv0 = 1.0f / l0, inv1 = 1.0f / l1;
    float* base0 = CTX + ((size_t)(b * SEQ + row0g)) * DM + h * HDIM + kh * 128;
    float* base1 = CTX + ((size_t)(b * SEQ + row1g)) * DM + h * HDIM + kh * 128;
#pragma unroll
    for (int f = 0; f < 16; f++) {
        int d = f * 8 + (lane & 3) * 2;
        *(float2*)(base0 + d) = make_float2(out[f][0] * inv0, out[f][1] * inv0);
        *(float2*)(base1 + d) = make_float2(out[f][2] * inv1, out[f][3] * inv1);
    }
}

// ---------------------------------------------------------------------------
extern "C" void kernel_launch(void* const* d_in, const int* in_sizes, int n_in,
                              void* d_out, int out_size)
{
    const float* X   = (const float*)d_in[0];
    const int*   pos = (const int*)  d_in[1];
    const float* W[4] = { (const float*)d_in[2], (const float*)d_in[3],
                          (const float*)d_in[4], (const float*)d_in[5] };
    float* out = (float*)d_out;

    float *Qg, *Kg, *Vg, *CTX;
    float2* rope;
    __nv_bfloat16 *Xhi, *Xlo, *Chi, *Clo, *WThi, *WTlo;
    __nv_bfloat16 *Qph, *Qpl, *Kph, *Kpl, *Vph, *Vpl;
    cudaGetSymbolAddress((void**)&Qg,  g_Q);
    cudaGetSymbolAddress((void**)&Kg,  g_K);
    cudaGetSymbolAddress((void**)&Vg,  g_V);
    cudaGetSymbolAddress((void**)&CTX, g_CTX);
    cudaGetSymbolAddress((void**)&rope, g_rope);
    cudaGetSymbolAddress((void**)&Xhi, g_Xhi);
    cudaGetSymbolAddress((void**)&Xlo, g_Xlo);
    cudaGetSymbolAddress((void**)&Chi, g_Chi);
    cudaGetSymbolAddress((void**)&Clo, g_Clo);
    cudaGetSymbolAddress((void**)&WThi, g_WThi);
    cudaGetSymbolAddress((void**)&WTlo, g_WTlo);
    cudaGetSymbolAddress((void**)&Qph, g_Qph);
    cudaGetSymbolAddress((void**)&Qpl, g_Qpl);
    cudaGetSymbolAddress((void**)&Kph, g_Kph);
    cudaGetSymbolAddress((void**)&Kpl, g_Kpl);
    cudaGetSymbolAddress((void**)&Vph, g_Vph);
    cudaGetSymbolAddress((void**)&Vpl, g_Vpl);

    const int GEMM_SMEM = 1024 + 1024 + 3 * 32768;                   // 100352
    const int ATTN_SMEM = 1024 + 1024 + 8192 + 65536 + 2 * 65536;    // 206848
    cudaFuncSetAttribute(gemm_hmma, cudaFuncAttributeMaxDynamicSharedMemorySize, GEMM_SMEM);
    cudaFuncSetAttribute(attn_mma, cudaFuncAttributeMaxDynamicSharedMemorySize, ATTN_SMEM);

    // merged prep: split_rm(X) + 4x split_tr(W) + rope table
    prep_all<<<74240, 256>>>(X, Xhi, Xlo, W[0], W[1], W[2], W[3],
                             WThi, WTlo, pos, rope);

    // fused QKV projection (fp32 scatter to [B,H,S,HD])
    gemm_hmma<<<dim3(96, 32), 256, GEMM_SMEM>>>(Xhi, Xlo, WThi, WTlo, Qg, Kg, Vg, 1);

    // merged pack: pack_qk (rope fused) + pack_v
    pack_all<<<10240, 256>>>(Qg, Kg, Vg, rope, Qph, Qpl, Kph, Kpl, Vph, Vpl);

    // attention (writes fp32 CTX)
    attn_mma<<<dim3(32, 32), 256, ATTN_SMEM>>>(Qph, Qpl, Kph, Kpl, Vph, Vpl, CTX);

    // output projection
    split_rm_tiled<<<8192, 256>>>(CTX, Chi, Clo);
    gemm_hmma<<<dim3(32, 32), 256, GEMM_SMEM>>>(Chi, Clo, WThi + 3 * WSZ, WTlo + 3 * WSZ,
                                                out, nullptr, nullptr, 0);
}

// round 17
// speedup vs baseline: 1.5969x; 1.0059x over previous
#include <cuda_runtime.h>
#include <cuda_bf16.h>
#include <stdint.h>
#include <math.h>

#define MB   2
#define SEQ  2048
#define DM   4096
#define NH   16
#define HDIM 256
#define ROTD 64

#define BK 32
#define NKT2 128            // K-chunks of 32
#define BLK2 8192           // one 128x32 bf16 block, 64B-row swizzled
#define WSZ ((size_t)DM * DM)

// ---------------- scratch ----------------
__device__ float g_Q[(size_t)MB * NH * SEQ * HDIM];
__device__ float g_K[(size_t)MB * NH * SEQ * HDIM];
__device__ float g_V[(size_t)MB * NH * SEQ * HDIM];
__device__ float g_CTX[(size_t)MB * SEQ * DM];
__device__ float2 g_rope[(size_t)MB * SEQ * 32];

// tiled + swizzled bf16 operand images (128x32 blocks, 8KB each)
__device__ __align__(1024) __nv_bfloat16 g_Xhi[(size_t)DM * DM];
__device__ __align__(1024) __nv_bfloat16 g_Xlo[(size_t)DM * DM];
__device__ __align__(1024) __nv_bfloat16 g_Chi[(size_t)DM * DM];
__device__ __align__(1024) __nv_bfloat16 g_Clo[(size_t)DM * DM];
__device__ __align__(1024) __nv_bfloat16 g_WThi[4][(size_t)DM * DM];
__device__ __align__(1024) __nv_bfloat16 g_WTlo[4][(size_t)DM * DM];

// attention packed operands
__device__ __align__(1024) __nv_bfloat16 g_Qph[(size_t)32 * 2048 * 256];
__device__ __align__(1024) __nv_bfloat16 g_Qpl[(size_t)32 * 2048 * 256];
__device__ __align__(1024) __nv_bfloat16 g_Kph[(size_t)32 * 2048 * 256];
__device__ __align__(1024) __nv_bfloat16 g_Kpl[(size_t)32 * 2048 * 256];
__device__ __align__(1024) __nv_bfloat16 g_Vph[(size_t)32 * 2048 * 256];
__device__ __align__(1024) __nv_bfloat16 g_Vpl[(size_t)32 * 2048 * 256];

// ---------------- helpers ----------------
__device__ __forceinline__ uint32_t smem_to_u32(const void* p) {
    uint32_t a;
    asm("{ .reg .u64 t; cvta.to.shared.u64 t, %1; cvt.u32.u64 %0, t; }" : "=r"(a) : "l"(p));
    return a;
}
#define MBARRIER_INIT(a, c) \
    asm volatile("mbarrier.init.shared.b64 [%0], %1;" :: "r"((uint32_t)(a)), "r"((uint32_t)(c)) : "memory")
#define MBARRIER_EXPECT_TX(a, tx) \
    asm volatile("mbarrier.arrive.expect_tx.shared.b64 _, [%0], %1;" :: "r"((uint32_t)(a)), "r"((uint32_t)(tx)) : "memory")
#define MBARRIER_ARRIVE(a) \
    asm volatile("mbarrier.arrive.shared.b64 _, [%0];" :: "r"((uint32_t)(a)) : "memory")
#define FENCE_PROXY_ASYNC() asm volatile("fence.proxy.async.shared::cta;" ::: "memory")
#define MBARRIER_WAIT_PARITY(mbar_smem_addr, phase_parity) do { \
    uint32_t _mbar = (uint32_t)(mbar_smem_addr); \
    uint32_t _parity = (uint32_t)(phase_parity); \
    uint32_t _done; \
    asm volatile("{\n\t.reg .pred p;\n\t" \
        "mbarrier.try_wait.parity.acquire.cta.shared::cta.b64 p, [%1], %2;\n\t" \
        "selp.b32 %0, 1, 0, p;\n\t}" \
        : "=r"(_done) : "r"(_mbar), "r"(_parity) : "memory"); \
    if (!_done) { \
        asm volatile("{\n\t.reg .pred P1;\n\t" \
            "WAIT_LOOP_%=:\n\t" \
            "mbarrier.try_wait.parity.acquire.cta.shared::cta.b64 P1, [%0], %1, 0x989680;\n\t" \
            "@P1 bra.uni WAIT_DONE_%=;\n\t" \
            "bra.uni WAIT_LOOP_%=;\n\t" \
            "WAIT_DONE_%=:\n\t}" \
            :: "r"(_mbar), "r"(_parity) : "memory"); \
    } \
} while(0)

__device__ __forceinline__ void tma_bulk(uint32_t dst, const void* src, uint32_t bytes, uint32_t mbar) {
    asm volatile("cp.async.bulk.shared::cluster.global.mbarrier::complete_tx::bytes [%0], [%1], %2, [%3];"
        :: "r"(dst), "l"(src), "r"(bytes), "r"(mbar) : "memory");
}

#define SMEM_SWIZZLE_128B(x) ((x) ^ (((x) >> 3) & 0x70))
__device__ __forceinline__ uint32_t swz64(int r, int c) {
    return (uint32_t)(r * 64 + ((c ^ ((r >> 1) & 3)) << 4));
}

#define LDSM4(r, addr) \
    asm volatile("ldmatrix.sync.aligned.m8n8.x4.shared.b16 {%0,%1,%2,%3}, [%4];" \
        : "=r"((r)[0]), "=r"((r)[1]), "=r"((r)[2]), "=r"((r)[3]) : "r"(addr))

__device__ __forceinline__ void mma16816(float* c, const uint32_t* a, uint32_t b0, uint32_t b1) {
    asm volatile("mma.sync.aligned.m16n8k16.row.col.f32.bf16.bf16.f32 "
        "{%0,%1,%2,%3}, {%4,%5,%6,%7}, {%8,%9}, {%0,%1,%2,%3};"
        : "+f"(c[0]), "+f"(c[1]), "+f"(c[2]), "+f"(c[3])
        : "r"(a[0]), "r"(a[1]), "r"(a[2]), "r"(a[3]), "r"(b0), "r"(b1));
}

__device__ __forceinline__ float ex2(float x) {
    float r;
    asm("ex2.approx.f32 %0, %1;" : "=f"(r) : "f"(x));
    return r;
}

__device__ __forceinline__ void split1(float v, __nv_bfloat16& h, __nv_bfloat16& l) {
    h = __float2bfloat16(v);
    l = __float2bfloat16(v - __bfloat162float(h));
}
__device__ __forceinline__ uint32_t pk2(float a, float b) {
    __nv_bfloat162 t = __floats2bfloat162_rn(a, b);
    return *(uint32_t*)&t;
}
__device__ __forceinline__ void pksplit2(float a, float b, uint32_t& hi, uint32_t& lo) {
    __nv_bfloat16 ah = __float2bfloat16(a), bh = __float2bfloat16(b);
    __nv_bfloat162 hp; hp.x = ah; hp.y = bh;
    hi = *(uint32_t*)&hp;
    lo = pk2(a - __bfloat162float(ah), b - __bfloat162float(bh));
}

// ---------------------------------------------------------------------------
// prep_all: merged split_rm(X) + 4x split_tr(W) + rope_tab in ONE grid.
// ---------------------------------------------------------------------------
__global__ void __launch_bounds__(256) prep_all(
    const float* __restrict__ X,
    __nv_bfloat16* __restrict__ Xhi, __nv_bfloat16* __restrict__ Xlo,
    const float* __restrict__ W0, const float* __restrict__ W1,
    const float* __restrict__ W2, const float* __restrict__ W3,
    __nv_bfloat16* __restrict__ WThi, __nv_bfloat16* __restrict__ WTlo,
    const int* __restrict__ pos, float2* __restrict__ tab)
{
    __shared__ float t[32][33];
    const int bid = blockIdx.x, tid = threadIdx.x;

    if (bid < 8192) {
        size_t idx = (size_t)bid * 256 + tid;
        int m  = (int)(idx >> 9);
        int k  = (int)(idx & 511) << 3;
        const float4* p = (const float4*)(X + ((size_t)m << 12) + k);
        float4 v0 = p[0], v1 = p[1];
        __nv_bfloat16 h[8], l[8];
        split1(v0.x, h[0], l[0]); split1(v0.y, h[1], l[1]);
        split1(v0.z, h[2], l[2]); split1(v0.w, h[3], l[3]);
        split1(v1.x, h[4], l[4]); split1(v1.y, h[5], l[5]);
        split1(v1.z, h[6], l[6]); split1(v1.w, h[7], l[7]);
        int mt = m >> 7, r = m & 127, kt = k >> 5, c = (k >> 3) & 3;
        size_t base = ((size_t)(mt * NKT2 + kt)) * BLK2 + swz64(r, c);
        *(uint4*)((char*)Xhi + base) = *(uint4*)h;
        *(uint4*)((char*)Xlo + base) = *(uint4*)l;
    } else if (bid < 73728) {
        const int q = bid - 8192;
        const int wsel = q >> 14;
        const int inner = q & 16383;
        const float* W = (wsel == 0) ? W0 : (wsel == 1) ? W1 : (wsel == 2) ? W2 : W3;
        __nv_bfloat16* Thi = WThi + (size_t)wsel * WSZ;
        __nv_bfloat16* Tlo = WTlo + (size_t)wsel * WSZ;
        const int nb = (inner & 127) * 32;
        const int kb = (inner >> 7) * 32;

        int tx = tid & 31, ty = tid >> 5;
#pragma unroll
        for (int j = 0; j < 4; j++)
            t[ty + j * 8][tx] = W[(size_t)(kb + ty + j * 8) * DM + nb + tx];
        __syncthreads();

        int half = tid >> 7, w7 = tid & 127;
        int nn = w7 >> 2, kc = (w7 & 3) * 8;
        int n = nb + nn, kk = kb + kc;
        float v[8];
#pragma unroll
        for (int qq = 0; qq < 8; qq++) v[qq] = t[kc + qq][nn];

        int nt = n >> 7, r = n & 127, kt = kk >> 5, c = (kk >> 3) & 3;
        size_t base = ((size_t)(nt * NKT2 + kt)) * BLK2 + swz64(r, c);
        __nv_bfloat16 o[8];
        if (half == 0) {
#pragma unroll
            for (int qq = 0; qq < 8; qq++) o[qq] = __float2bfloat16(v[qq]);
            *(uint4*)((char*)Thi + base) = *(uint4*)o;
        } else {
#pragma unroll
            for (int qq = 0; qq < 8; qq++) {
                __nv_bfloat16 hh = __float2bfloat16(v[qq]);
                o[qq] = __float2bfloat16(v[qq] - __bfloat162float(hh));
            }
            *(uint4*)((char*)Tlo + base) = *(uint4*)o;
        }
    } else {
        int idx = (bid - 73728) * 256 + tid;
        if (idx < MB * SEQ * 32) {
            int i = idx & 31, s = (idx >> 5) & (SEQ - 1), b = idx >> 16;
            int p = pos[b * SEQ + s];
            double inv = pow(10000.0, -(double)(2 * i) / (double)ROTD);
            double sn, cs;
            sincos((double)p * inv, &sn, &cs);
            tab[idx] = make_float2((float)cs, (float)sn);
        }
    }
}

// ---------------------------------------------------------------------------
// HMMA split-bf16 GEMM (round-9 best): 128x128 CTA, BK=32, 3 stages, 2 CTAs/SM
// ---------------------------------------------------------------------------
__global__ void __launch_bounds__(256, 2) gemm_hmma(
    const __nv_bfloat16* __restrict__ Ahi, const __nv_bfloat16* __restrict__ Alo,
    const __nv_bfloat16* __restrict__ Bhi, const __nv_bfloat16* __restrict__ Blo,
    float* __restrict__ C0, float* __restrict__ C1, float* __restrict__ C2,
    int mode)
{
    extern __shared__ char gsm[];
    uint32_t sb = (smem_to_u32(gsm) + 1023u) & ~1023u;
    const uint32_t stage0 = sb + 1024u;                   // 3 stages x 32KB
    const int tid = threadIdx.x, wid = tid >> 5, lane = tid & 31;
    const int bm = blockIdx.y * 128;
    const int bn_g = blockIdx.x * 128;
    const int wm = wid >> 2, wn = wid & 3;                // 2(M) x 4(N)

    if (tid == 0) {
#pragma unroll
        for (int s = 0; s < 3; s++) {
            MBARRIER_INIT(sb + s * 8, 1);
            MBARRIER_INIT(sb + 24 + s * 8, 256);
        }
        FENCE_PROXY_ASYNC();
    }
    __syncthreads();

    const char* pAh = (const char*)Ahi + ((size_t)blockIdx.y << 20);
    const char* pAl = (const char*)Alo + ((size_t)blockIdx.y << 20);
    const char* pBh = (const char*)Bhi + ((size_t)blockIdx.x << 20);
    const char* pBl = (const char*)Blo + ((size_t)blockIdx.x << 20);

    auto issue = [&](int j) {
        const int s = j % 3;
        const uint32_t st = stage0 + (uint32_t)s * 32768u;
        const uint32_t mb = sb + (uint32_t)s * 8u;
        const size_t off = (size_t)j << 13;
        MBARRIER_EXPECT_TX(mb, 32768u);
        tma_bulk(st,           pAh + off, 8192u, mb);
        tma_bulk(st + 8192u,   pAl + off, 8192u, mb);
        tma_bulk(st + 16384u,  pBh + off, 8192u, mb);
        tma_bulk(st + 24576u,  pBl + off, 8192u, mb);
    };
    if (tid == 0) { issue(0); issue(1); issue(2); }

    float acc[16][4];
#pragma unroll
    for (int i = 0; i < 16; i++)
#pragma unroll
        for (int j = 0; j < 4; j++) acc[i][j] = 0.f;

    const int ra = lane & 15, c4 = lane >> 4;
    const int rb = (lane & 7) + 8 * ((lane >> 3) & 1);

    int fph[3] = {0, 0, 0};
    int eph[3] = {0, 0, 0};
    for (int i = 0; i < NKT2; i++) {
        const int s = i % 3;
        const uint32_t st = stage0 + (uint32_t)s * 32768u;
        MBARRIER_WAIT_PARITY(sb + s * 8, fph[s]); fph[s] ^= 1;

#pragma unroll
        for (int ks = 0; ks < 2; ks++) {
            uint32_t bh[2][4], bl[2][4];
#pragma unroll
            for (int ip = 0; ip < 2; ip++) {
                uint32_t off = swz64(wn * 32 + ip * 16 + rb, ks * 2 + c4);
                LDSM4(bh[ip], st + 16384u + off);
                LDSM4(bl[ip], st + 24576u + off);
            }
#pragma unroll
            for (int im = 0; im < 4; im++) {
                uint32_t off = swz64(wm * 64 + im * 16 + ra, ks * 2 + c4);
                uint32_t ah[4], al[4];
                LDSM4(ah, st + off);
                LDSM4(al, st + 8192u + off);
#pragma unroll
                for (int in = 0; in < 4; in++) {
                    const int ip = in >> 1, sel = in & 1;
                    float* c = acc[im * 4 + in];
                    mma16816(c, ah, bh[ip][sel], bh[ip][sel + 2]);
                    mma16816(c, ah, bl[ip][sel], bl[ip][sel + 2]);
                    mma16816(c, al, bh[ip][sel], bh[ip][sel + 2]);
                }
            }
        }
        MBARRIER_ARRIVE(sb + 24 + s * 8);
        if (tid == 0 && i + 3 < NKT2) {
            MBARRIER_WAIT_PARITY(sb + 24 + s * 8, eph[s]); eph[s] ^= 1;
            issue(i + 3);
        }
    }

    const int tsel = bn_g >> 12;
    const int bn = bn_g & 4095;
    float* Cout = (tsel == 0) ? C0 : ((tsel == 1) ? C1 : C2);
#pragma unroll
    for (int im = 0; im < 4; im++) {
#pragma unroll
        for (int in = 0; in < 4; in++) {
            const float* c = acc[im * 4 + in];
            int m0 = bm + wm * 64 + im * 16 + (lane >> 2);
            int n  = bn + wn * 32 + in * 8 + (lane & 3) * 2;
#pragma unroll
            for (int half = 0; half < 2; half++) {
                int m = m0 + half * 8;
                float2 v = make_float2(c[half * 2], c[half * 2 + 1]);
                if (mode == 0) {
                    *(float2*)(C0 + (size_t)m * DM + n) = v;
                } else {
                    int b = m >> 11, sq = m & 2047, h = n >> 8, hd = n & 255;
                    *(float2*)(Cout + ((size_t)(b * NH + h) * SEQ + sq) * HDIM + hd) = v;
                }
            }
        }
    }
}

// ---------------------------------------------------------------------------
// split_rm (standalone, for CTX before the output projection)
// ---------------------------------------------------------------------------
__global__ void __launch_bounds__(256) split_rm_tiled(const float* __restrict__ in,
                                                      __nv_bfloat16* __restrict__ hi,
                                                      __nv_bfloat16* __restrict__ lo)
{
    size_t idx = (size_t)blockIdx.x * 256 + threadIdx.x;
    int m  = (int)(idx >> 9);
    int k  = (int)(idx & 511) << 3;
    const float4* p = (const float4*)(in + ((size_t)m << 12) + k);
    float4 v0 = p[0], v1 = p[1];

    __nv_bfloat16 h[8], l[8];
    split1(v0.x, h[0], l[0]); split1(v0.y, h[1], l[1]);
    split1(v0.z, h[2], l[2]); split1(v0.w, h[3], l[3]);
    split1(v1.x, h[4], l[4]); split1(v1.y, h[5], l[5]);
    split1(v1.z, h[6], l[6]); split1(v1.w, h[7], l[7]);

    int mt = m >> 7, r = m & 127, kt = k >> 5, c = (k >> 3) & 3;
    size_t base = ((size_t)(mt * NKT2 + kt)) * BLK2 + swz64(r, c);
    *(uint4*)((char*)hi + base) = *(uint4*)h;
    *(uint4*)((char*)lo + base) = *(uint4*)l;
}

// ---------------------------------------------------------------------------
// pack_all: merged pack_qk (rope fused) + pack_v in ONE grid.
// ---------------------------------------------------------------------------
__global__ void __launch_bounds__(256) pack_all(
    const float* __restrict__ Q, const float* __restrict__ K, const float* __restrict__ V,
    const float2* __restrict__ tab,
    __nv_bfloat16* __restrict__ Qh, __nv_bfloat16* __restrict__ Ql,
    __nv_bfloat16* __restrict__ Kh, __nv_bfloat16* __restrict__ Kl,
    __nv_bfloat16* __restrict__ Vh, __nv_bfloat16* __restrict__ Vl)
{
    __shared__ float sm[32][257];
    const int bid = blockIdx.x, t = threadIdx.x;

    if (bid < 8192) {
        size_t idx = (size_t)bid * 256 + t;
        int c0 = (int)(idx & 31) << 3;
        int s  = (int)(idx >> 5) & 2047;
        int bh = (int)(idx >> 16);
        int b  = bh >> 4;

        int st = s >> 5, r = s & 31, ct = c0 >> 6, cc = c0 & 63;
        size_t dst = (((size_t)(bh * 64 + st) * 4 + ct) << 12)
                   + SMEM_SWIZZLE_128B((uint32_t)(r * 128 + cc * 2));
        size_t src = ((size_t)bh * SEQ + s) * HDIM + c0;

        float2 rt[4];
        const bool dorope = (c0 < ROTD);
        if (dorope) {
#pragma unroll
            for (int q = 0; q < 4; q++)
                rt[q] = tab[(size_t)(b * SEQ + s) * 32 + (c0 >> 1) + q];
        }

        {
            const float4* p = (const float4*)(Q + src);
            float4 v0 = p[0], v1 = p[1];
            float vv[8] = {v0.x, v0.y, v0.z, v0.w, v1.x, v1.y, v1.z, v1.w};
            if (dorope) {
#pragma unroll
                for (int q = 0; q < 4; q++) {
                    float x = vv[2 * q], y = vv[2 * q + 1];
                    vv[2 * q]     = x * rt[q].x - y * rt[q].y;
                    vv[2 * q + 1] = y * rt[q].x + x * rt[q].y;
                }
            }
            __nv_bfloat16 h[8], l[8];
#pragma unroll
            for (int q = 0; q < 8; q++) split1(vv[q], h[q], l[q]);
            *(uint4*)((char*)Qh + dst) = *(uint4*)h;
            *(uint4*)((char*)Ql + dst) = *(uint4*)l;
        }
        {
            const float4* p = (const float4*)(K + src);
            float4 v0 = p[0], v1 = p[1];
            float vv[8] = {v0.x, v0.y, v0.z, v0.w, v1.x, v1.y, v1.z, v1.w};
            if (dorope) {
#pragma unroll
                for (int q = 0; q < 4; q++) {
                    float x = vv[2 * q], y = vv[2 * q + 1];
                    vv[2 * q]     = x * rt[q].x - y * rt[q].y;
                    vv[2 * q + 1] = y * rt[q].x + x * rt[q].y;
                }
            }
            __nv_bfloat16 h[8], l[8];
#pragma unroll
            for (int q = 0; q < 8; q++) split1(vv[q], h[q], l[q]);
            *(uint4*)((char*)Kh + dst) = *(uint4*)h;
            *(uint4*)((char*)Kl + dst) = *(uint4*)l;
        }
    } else {
        const int inner = bid - 8192;
        const int jt = inner & 63, bh = inner >> 6;
        int r = t >> 3, d0 = (t & 7) * 32;
        const float* src = V + ((size_t)bh * SEQ + jt * 32 + r) * HDIM + d0;
#pragma unroll
        for (int i = 0; i < 8; i++) {
            float4 v = *(const float4*)(src + i * 4);
            sm[r][d0 + i * 4 + 0] = v.x; sm[r][d0 + i * 4 + 1] = v.y;
            sm[r][d0 + i * 4 + 2] = v.z; sm[r][d0 + i * 4 + 3] = v.w;
        }
        __syncthreads();

        int d = t;
        int dt = d >> 7, rd = d & 127;
        size_t base = ((size_t)(bh * 64 + jt) * 2 + dt) << 13;
#pragma unroll
        for (int c = 0; c < 4; c++) {
            __nv_bfloat16 h[8], l[8];
#pragma unroll
            for (int jj = 0; jj < 8; jj++) split1(sm[c * 8 + jj][d], h[jj], l[jj]);
            size_t off = base + swz64(rd, c);
            *(uint4*)((char*)Vh + off) = *(uint4*)h;
            *(uint4*)((char*)Vl + off) = *(uint4*)l;
        }
    }
}

// ---------------------------------------------------------------------------
// HMMA causal flash attention (round-14 + Q-hi register hoist).
// 256 threads, warp (mq, kh): Q-hi frags hoisted into 64 regs before the
// mainloop (Q smem is immutable); score phase loads only Q-lo/K from smem.
// P frags exchanged through smem; PV over ALL 32 keys but only the warp's
// own 128-d half -> out[16][4]; direct epilogue write.
// ---------------------------------------------------------------------------
__global__ void __launch_bounds__(256, 1) attn_mma(
    const __nv_bfloat16* __restrict__ Qph, const __nv_bfloat16* __restrict__ Qpl,
    const __nv_bfloat16* __restrict__ Kph, const __nv_bfloat16* __restrict__ Kpl,
    const __nv_bfloat16* __restrict__ Vph, const __nv_bfloat16* __restrict__ Vpl,
    float* __restrict__ CTX)
{
    extern __shared__ char gsm[];
    const uint32_t g0 = smem_to_u32(gsm);
    const uint32_t sb = (g0 + 1023u) & ~1023u;
    float* mbuf = (float*)(gsm + (sb - g0) + 128);    // 128 floats
    float* sbuf = mbuf + 128;                         // 128 floats
    uint32_t* pbuf = (uint32_t*)(gsm + (sb - g0) + 2048);  // 8KB P exchange
    const uint32_t sq = sb + 10240u;                  // Q: hi 32KB, lo 32KB
    const uint32_t sv = sq + 65536u;                  // 2 stages x 64KB

    const int qt = (int)gridDim.x - 1 - (int)blockIdx.x;
    const int bh = blockIdx.y;
    const int b  = bh >> 4, h = bh & 15;
    const int tid = threadIdx.x, w = tid >> 5, lane = tid & 31;
    const int mq = w & 3, kh = w >> 2;
    const int nkt = 2 * qt + 2;

    if (tid == 0) {
        MBARRIER_INIT(sb, 1);
        MBARRIER_INIT(sb + 8, 1);
        MBARRIER_INIT(sb + 16, 1);
        MBARRIER_INIT(sb + 24, 256);
        MBARRIER_INIT(sb + 32, 256);
        FENCE_PROXY_ASYNC();
    }
    __syncthreads();

    auto issueKV = [&](int kt, int s) {
        const uint32_t st = sv + (uint32_t)s * 65536u;
        const uint32_t mb = sb + 8 + (uint32_t)s * 8u;
        MBARRIER_EXPECT_TX(mb, 65536u);
        size_t kbase = ((size_t)(bh * 64 + kt) * 4) << 12;
#pragma unroll
        for (int ct = 0; ct < 4; ct++) {
            tma_bulk(st + ct * 4096,          (const char*)Kph + kbase + ct * 4096, 4096u, mb);
            tma_bulk(st + 16384 + ct * 4096,  (const char*)Kpl + kbase + ct * 4096, 4096u, mb);
        }
        size_t vbase = ((size_t)(bh * 64 + kt) * 2) << 13;
#pragma unroll
        for (int dt = 0; dt < 2; dt++) {
            tma_bulk(st + 32768 + dt * 8192,  (const char*)Vph + vbase + dt * 8192, 8192u, mb);
            tma_bulk(st + 49152 + dt * 8192,  (const char*)Vpl + vbase + dt * 8192, 8192u, mb);
        }
    };

    if (tid == 0) {
        MBARRIER_EXPECT_TX(sb, 65536u);
#pragma unroll
        for (int sb2 = 0; sb2 < 2; sb2++) {
            size_t qbase = ((size_t)(bh * 64 + qt * 2 + sb2) * 4) << 12;
#pragma unroll
            for (int ct = 0; ct < 4; ct++) {
                tma_bulk(sq + (sb2 * 4 + ct) * 4096,          (const char*)Qph + qbase + ct * 4096, 4096u, sb);
                tma_bulk(sq + 32768 + (sb2 * 4 + ct) * 4096,  (const char*)Qpl + qbase + ct * 4096, 4096u, sb);
            }
        }
        issueKV(0, 0);
        issueKV(1, 1);
    }

    float out[16][4];
#pragma unroll
    for (int i = 0; i < 16; i++)
#pragma unroll
        for (int j = 0; j < 4; j++) out[i][j] = 0.f;
    float m0 = -1e30f, m1 = -1e30f, l0 = 0.f, l1 = 0.f;

    const int ra = lane & 15;
    const int rb = (lane & 7) + 8 * ((lane >> 3) & 1);
    const int qrow = (mq & 1) * 16 + ra;
    const int row0g = qt * 64 + mq * 16 + (lane >> 2);
    const int row1g = row0g + 8;
    const int xrow0 = mq * 16 + (lane >> 2);
    const int pme = w * 256 + lane;
    const int ppr = ((kh ^ 1) * 4 + mq) * 256 + lane;
    const float SC = 0.0901699438f;

    MBARRIER_WAIT_PARITY(sb, 0);

    // ---- hoist Q-hi fragments into registers (Q smem is immutable) ----
    uint32_t qh[16][4];
#pragma unroll
    for (int kk = 0; kk < 16; kk++) {
        uint32_t aoff = (uint32_t)(((mq >> 1) * 4 + (kk >> 2)) * 4096)
                      + SMEM_SWIZZLE_128B((uint32_t)(qrow * 128 + (kk & 3) * 32 + (lane >> 4) * 16));
        LDSM4(qh[kk], sq + aoff);
    }

    int fph0 = 0, fph1 = 0, eph0 = 0, eph1 = 0;
    for (int kt = 0; kt < nkt; kt++) {
        const int s = kt & 1;
        const uint32_t st = sv + (uint32_t)s * 65536u;
        if (s == 0) { MBARRIER_WAIT_PARITY(sb + 8, fph0);  fph0 ^= 1; }
        else        { MBARRIER_WAIT_PARITY(sb + 16, fph1); fph1 ^= 1; }

        // ---- scores for this warp's 16 keys ----
        float sc[2][4];
#pragma unroll
        for (int f = 0; f < 2; f++)
#pragma unroll
            for (int j = 0; j < 4; j++) sc[f][j] = 0.f;

#pragma unroll
        for (int kk = 0; kk < 16; kk++) {
            uint32_t al[4], kfh[4], kfl[4];
            uint32_t aoff = (uint32_t)(((mq >> 1) * 4 + (kk >> 2)) * 4096)
                          + SMEM_SWIZZLE_128B((uint32_t)(qrow * 128 + (kk & 3) * 32 + (lane >> 4) * 16));
            LDSM4(al, sq + 32768u + aoff);
            uint32_t koff = (uint32_t)((kk >> 2) * 4096)
                          + SMEM_SWIZZLE_128B((uint32_t)((kh * 16 + rb) * 128 + (kk & 3) * 32 + (lane >> 4) * 16));
            LDSM4(kfh, st + koff);
            LDSM4(kfl, st + 16384u + koff);
#pragma unroll
            for (int f = 0; f < 2; f++) {
                mma16816(sc[f], qh[kk], kfh[f], kfh[f + 2]);
                mma16816(sc[f], qh[kk], kfl[f], kfl[f + 2]);
                mma16816(sc[f], al,     kfh[f], kfh[f + 2]);
            }
        }

        // ---- mask + local max ----
        const bool domask = (kt * 32 + kh * 16 + 15) > (qt * 64 + mq * 16);
        float tm0 = -1e30f, tm1 = -1e30f;
#pragma unroll
        for (int f = 0; f < 2; f++) {
#pragma unroll
            for (int j = 0; j < 4; j++) {
                float v = sc[f][j] * SC;
                if (domask) {
                    int col = kt * 32 + kh * 16 + f * 8 + (lane & 3) * 2 + (j & 1);
                    int row = (j < 2) ? row0g : row1g;
                    if (col > row) v = -1e30f;
                }
                sc[f][j] = v;
                if (j < 2) tm0 = fmaxf(tm0, v); else tm1 = fmaxf(tm1, v);
            }
        }
        tm0 = fmaxf(tm0, __shfl_xor_sync(0xffffffffu, tm0, 1));
        tm0 = fmaxf(tm0, __shfl_xor_sync(0xffffffffu, tm0, 2));
        tm1 = fmaxf(tm1, __shfl_xor_sync(0xffffffffu, tm1, 1));
        tm1 = fmaxf(tm1, __shfl_xor_sync(0xffffffffu, tm1, 2));

        // ---- cross-warp max exchange (sync 1) ----
        if ((lane & 3) == 0) {
            mbuf[kh * 64 + xrow0]     = tm0;
            mbuf[kh * 64 + xrow0 + 8] = tm1;
        }
        __syncthreads();
        tm0 = fmaxf(tm0, mbuf[(kh ^ 1) * 64 + xrow0]);
        tm1 = fmaxf(tm1, mbuf[(kh ^ 1) * 64 + xrow0 + 8]);

        float nm0 = fmaxf(m0, tm0), nm1 = fmaxf(m1, tm1);
        float a0 = ex2(m0 - nm0), a1 = ex2(m1 - nm1);
        float ls0 = 0.f, ls1 = 0.f;
#pragma unroll
        for (int f = 0; f < 2; f++) {
            sc[f][0] = ex2(sc[f][0] - nm0); ls0 += sc[f][0];
            sc[f][1] = ex2(sc[f][1] - nm0); ls0 += sc[f][1];
            sc[f][2] = ex2(sc[f][2] - nm1); ls1 += sc[f][2];
            sc[f][3] = ex2(sc[f][3] - nm1); ls1 += sc[f][3];
        }
        ls0 += __shfl_xor_sync(0xffffffffu, ls0, 1);
        ls0 += __shfl_xor_sync(0xffffffffu, ls0, 2);
        ls1 += __shfl_xor_sync(0xffffffffu, ls1, 1);
        ls1 += __shfl_xor_sync(0xffffffffu, ls1, 2);

        // ---- P frags (bf16 hi/lo) ----
        uint32_t pah[4], pal[4];
        pksplit2(sc[0][0], sc[0][1], pah[0], pal[0]);
        pksplit2(sc[0][2], sc[0][3], pah[1], pal[1]);
        pksplit2(sc[1][0], sc[1][1], pah[2], pal[2]);
        pksplit2(sc[1][2], sc[1][3], pah[3], pal[3]);

        // ---- sum + P exchange (sync 2) ----
        if ((lane & 3) == 0) {
            sbuf[kh * 64 + xrow0]     = ls0;
            sbuf[kh * 64 + xrow0 + 8] = ls1;
        }
#pragma unroll
        for (int i = 0; i < 4; i++) {
            pbuf[pme + i * 32]        = pah[i];
            pbuf[pme + (4 + i) * 32]  = pal[i];
        }
        __syncthreads();
        ls0 += sbuf[(kh ^ 1) * 64 + xrow0];
        ls1 += sbuf[(kh ^ 1) * 64 + xrow0 + 8];

        uint32_t qah[4], qal[4];
#pragma unroll
        for (int i = 0; i < 4; i++) {
            qah[i] = pbuf[ppr + i * 32];
            qal[i] = pbuf[ppr + (4 + i) * 32];
        }

        l0 = l0 * a0 + ls0; l1 = l1 * a1 + ls1;
        m0 = nm0; m1 = nm1;

#pragma unroll
        for (int i = 0; i < 16; i++) {
            out[i][0] *= a0; out[i][1] *= a0;
            out[i][2] *= a1; out[i][3] *= a1;
        }

        // ---- out += P x V^T: all 32 keys, own 128-d half (dt = kh) ----
        const uint32_t vbase = st + 32768u + (uint32_t)kh * 8192u;
#pragma unroll
        for (int kc = 0; kc < 2; kc++) {
            const uint32_t* uh = (kc == kh) ? pah : qah;
            const uint32_t* ul = (kc == kh) ? pal : qal;
#pragma unroll
            for (int dp = 0; dp < 8; dp++) {
                uint32_t vh[4], vl[4];
                int rr = dp * 16 + rb;
                uint32_t voff = swz64(rr, kc * 2 + (lane >> 4));
                LDSM4(vh, vbase + voff);
                LDSM4(vl, vbase + 16384u + voff);
#pragma unroll
                for (int sel = 0; sel < 2; sel++) {
                    float* c = out[2 * dp + sel];
                    mma16816(c, uh, vh[sel], vh[sel + 2]);
                    mma16816(c, uh, vl[sel], vl[sel + 2]);
                    mma16816(c, ul, vh[sel], vh[sel + 2]);
                }
            }
        }

        MBARRIER_ARRIVE(sb + 24 + s * 8);
        if (tid == 0 && kt + 2 < nkt) {
            if (s == 0) { MBARRIER_WAIT_PARITY(sb + 24, eph0); eph0 ^= 1; }
            else        { MBARRIER_WAIT_PARITY(sb + 32, eph1); eph1 ^= 1; }
            issueKV(kt + 2, s);
        }
    }

    // ---- epilogue: direct write, warps own disjoint (rows, d-half) ----
    float inv0 = 1.0f / l0, inv1 = 1.0f / l1;
    float* base0 = CTX + ((size_t)(b * SEQ + row0g)) * DM + h * HDIM + kh * 128;
    float* base1 = CTX + ((size_t)(b * SEQ + row1g)) * DM + h * HDIM + kh * 128;
#pragma unroll
    for (int f = 0; f < 16; f++) {
        int d = f * 8 + (lane & 3) * 2;
        *(float2*)(base0 + d) = make_float2(out[f][0] * inv0, out[f][1] * inv0);
        *(float2*)(base1 + d) = make_float2(out[f][2] * inv1, out[f][3] * inv1);
    }
}

// ---------------------------------------------------------------------------
extern "C" void kernel_launch(void* const* d_in, const int* in_sizes, int n_in,
                              void* d_out, int out_size)
{
    const float* X   = (const float*)d_in[0];
    const int*   pos = (const int*)  d_in[1];
    const float* W[4] = { (const float*)d_in[2], (const float*)d_in[3],
                          (const float*)d_in[4], (const float*)d_in[5] };
    float* out = (float*)d_out;

    float *Qg, *Kg, *Vg, *CTX;
    float2* rope;
    __nv_bfloat16 *Xhi, *Xlo, *Chi, *Clo, *WThi, *WTlo;
    __nv_bfloat16 *Qph, *Qpl, *Kph, *Kpl, *Vph, *Vpl;
    cudaGetSymbolAddress((void**)&Qg,  g_Q);
    cudaGetSymbolAddress((void**)&Kg,  g_K);
    cudaGetSymbolAddress((void**)&Vg,  g_V);
    cudaGetSymbolAddress((void**)&CTX, g_CTX);
    cudaGetSymbolAddress((void**)&rope, g_rope);
    cudaGetSymbolAddress((void**)&Xhi, g_Xhi);
    cudaGetSymbolAddress((void**)&Xlo, g_Xlo);
    cudaGetSymbolAddress((void**)&Chi, g_Chi);
    cudaGetSymbolAddress((void**)&Clo, g_Clo);
    cudaGetSymbolAddress((void**)&WThi, g_WThi);
    cudaGetSymbolAddress((void**)&WTlo, g_WTlo);
    cudaGetSymbolAddress((void**)&Qph, g_Qph);
    cudaGetSymbolAddress((void**)&Qpl, g_Qpl);
    cudaGetSymbolAddress((void**)&Kph, g_Kph);
    cudaGetSymbolAddress((void**)&Kpl, g_Kpl);
    cudaGetSymbolAddress((void**)&Vph, g_Vph);
    cudaGetSymbolAddress((void**)&Vpl, g_Vpl);

    const int GEMM_SMEM = 1024 + 1024 + 3 * 32768;                   // 100352
    const int ATTN_SMEM = 1024 + 1024 + 8192 + 65536 + 2 * 65536;    // 206848
    cudaFuncSetAttribute(gemm_hmma, cudaFuncAttributeMaxDynamicSharedMemorySize, GEMM_SMEM);
    cudaFuncSetAttribute(attn_mma, cudaFuncAttributeMaxDynamicSharedMemorySize, ATTN_SMEM);

    // merged prep: split_rm(X) + 4x split_tr(W) + rope table
    prep_all<<<74240, 256>>>(X, Xhi, Xlo, W[0], W[1], W[2], W[3],
                             WThi, WTlo, pos, rope);

    // fused QKV projection (fp32 scatter to [B,H,S,HD])
    gemm_hmma<<<dim3(96, 32), 256, GEMM_SMEM>>>(Xhi, Xlo, WThi, WTlo, Qg, Kg, Vg, 1);

    // merged pack: pack_qk (rope fused) + pack_v
    pack_all<<<10240, 256>>>(Qg, Kg, Vg, rope, Qph, Qpl, Kph, Kpl, Vph, Vpl);

    // attention (writes fp32 CTX)
    attn_mma<<<dim3(32, 32), 256, ATTN_SMEM>>>(Qph, Qpl, Kph, Kpl, Vph, Vpl, CTX);

    // output projection
    split_rm_tiled<<<8192, 256>>>(CTX, Chi, Clo);
    gemm_hmma<<<dim3(32, 32), 256, GEMM_SMEM>>>(Chi, Clo, WThi + 3 * WSZ, WTlo + 3 * WSZ,
                                                out, nullptr, nullptr, 0);
}